// round 6
// baseline (speedup 1.0000x reference)
#include <cuda_runtime.h>
#include <mma.h>
#include <cstdint>

using namespace nvcuda;

// ---------------- problem constants ----------------
constexpr int NN = 50000;
constexpr int NE = 800000;
constexpr int IND = 64;
constexpr int HD = 128;
constexpr int NG = 1024;
constexpr float SLOPE = 0.01f;

constexpr int LDA = 132;   // smem leading dim

// ---------------- scratch (device globals) ----------------
__device__ __align__(256) float g_h0[(size_t)NN * HD];
__device__ __align__(256) float g_h1[(size_t)NN * HD];
__device__ __align__(256) float g_sums[(size_t)NG * HD];
__device__ __align__(256) float g_cnt[NG];
__device__ __align__(256) int   g_ei[2 * NE];
__device__ __align__(256) int   g_batch[NN];
__device__ __align__(256) int   g_deg[NN];
__device__ __align__(256) int   g_cur[NN];
__device__ __align__(256) int   g_rowstart[NN + 1];
__device__ __align__(256) int   g_csr[NE];
__device__ int g_is64;

// ============================================================
// index dtype detection + conversion
// ============================================================
__global__ void detect_dtype(const int* __restrict__ raw) {
    __shared__ int s_any;
    if (threadIdx.x == 0) s_any = 0;
    __syncthreads();
    int bad = 0;
    for (int i = threadIdx.x; i < 4096; i += blockDim.x) bad |= raw[2 * i + 1];
    if (bad) atomicOr(&s_any, 1);
    __syncthreads();
    if (threadIdx.x == 0) g_is64 = (s_any == 0) ? 1 : 0;
}
__global__ void convert_idx(const void* __restrict__ raw, int* __restrict__ out, int n) {
    int i = blockIdx.x * blockDim.x + threadIdx.x;
    if (i >= n) return;
    if (g_is64) out[i] = (int)((const long long*)raw)[i];
    else        out[i] = ((const int*)raw)[i];
}

// ============================================================
// CSR build: histogram -> scan -> fill
// ============================================================
__global__ void zero_deg() {
    int i = blockIdx.x * blockDim.x + threadIdx.x;
    if (i < NN) g_deg[i] = 0;
}
__global__ void hist_dst() {
    int e = blockIdx.x * blockDim.x + threadIdx.x;
    if (e < NE) atomicAdd(&g_deg[g_ei[NE + e]], 1);
}
__global__ void __launch_bounds__(1024) scan_deg() {
    __shared__ int part[1024];
    int tid = threadIdx.x;
    const int CH = (NN + 1023) / 1024;  // 49
    int base = tid * CH;
    int s = 0;
    for (int i = 0; i < CH; i++) {
        int idx = base + i;
        if (idx < NN) s += g_deg[idx];
    }
    part[tid] = s;
    __syncthreads();
    for (int off = 1; off < 1024; off <<= 1) {
        int v = (tid >= off) ? part[tid - off] : 0;
        __syncthreads();
        part[tid] += v;
        __syncthreads();
    }
    int run = (tid > 0) ? part[tid - 1] : 0;
    for (int i = 0; i < CH; i++) {
        int idx = base + i;
        if (idx < NN) {
            int d = g_deg[idx];
            g_rowstart[idx] = run;
            run += d;
        }
    }
    if (tid == 1023) g_rowstart[NN] = run;
    for (int i = tid; i < NN; i += 1024) g_cur[i] = 0;
}
__global__ void fill_csr() {
    int e = blockIdx.x * blockDim.x + threadIdx.x;
    if (e >= NE) return;
    int s = g_ei[e];
    int d = g_ei[NE + e];
    int p = atomicAdd(&g_cur[d], 1);
    g_csr[g_rowstart[d] + p] = s;
}

// ============================================================
// fused GIN layer: gather-aggregate (CSR) + two-GEMM MLP (wmma tf32)
//   A[row] = X[node] + sum_{src in csr[node]} X[src]
//   Out = relu( relu(A@W1 + b1) @ W2 + b2 + Res )
// L0: Res = x @ Wres computed on-chip; else Res = X[node].
// POOL: epilogue accumulates graph sums instead of writing h.
// Block: 256 threads = 8 warps; warp w owns rows [16w, 16w+16).
// ============================================================
template<int K1, bool L0, bool POOL>
__global__ void __launch_bounds__(256)
gin_fused(const float* __restrict__ X,
          const float* __restrict__ W1, const float* __restrict__ b1,
          const float* __restrict__ W2, const float* __restrict__ b2,
          const float* __restrict__ Wres,
          float* __restrict__ OutH) {
    extern __shared__ float sm[];
    float* sA = sm;                     // 128 x LDA (A tile, then T tile)
    float* sW = sm + 128 * LDA;         // 128 x LDA (weights, then D tile)
    float* sR = sm + 2 * 128 * LDA;     // 128 x LDA (L0 residual)

    int tid = threadIdx.x;
    int wid = tid >> 5;
    int lane = tid & 31;
    int r0 = blockIdx.x * 128;

    wmma::fragment<wmma::accumulator, 16, 16, 8, float> acc[8];

    auto loadW = [&](const float* __restrict__ src, int K) {
        int n4 = K * 32;
        for (int idx = tid; idx < n4; idx += 256) {
            int row = idx >> 5, c4 = idx & 31;
            float4 v = __ldg((const float4*)(src + (size_t)row * 128) + c4);
            *(float4*)(sW + row * LDA + c4 * 4) = v;
        }
    };
    auto mmaPhase = [&](int ksteps) {
#pragma unroll
        for (int n = 0; n < 8; n++) wmma::fill_fragment(acc[n], 0.f);
        for (int k = 0; k < ksteps; k++) {
            wmma::fragment<wmma::matrix_a, 16, 16, 8, wmma::precision::tf32, wmma::row_major> af;
            wmma::load_matrix_sync(af, sA + wid * 16 * LDA + k * 8, LDA);
#pragma unroll
            for (int i = 0; i < af.num_elements; i++) af.x[i] = wmma::__float_to_tf32(af.x[i]);
#pragma unroll
            for (int n = 0; n < 8; n++) {
                wmma::fragment<wmma::matrix_b, 16, 16, 8, wmma::precision::tf32, wmma::row_major> bf;
                wmma::load_matrix_sync(bf, sW + k * 8 * LDA + n * 16, LDA);
#pragma unroll
                for (int i = 0; i < bf.num_elements; i++) bf.x[i] = wmma::__float_to_tf32(bf.x[i]);
                wmma::mma_sync(acc[n], af, bf, acc[n]);
            }
        }
    };

    // ---- L0: load raw x tile, project R = x @ Wres -> sR ----
    if (L0) {
        for (int idx = tid; idx < 128 * 16; idx += 256) {
            int row = idx >> 4, c4 = idx & 15;
            float4 v = make_float4(0.f, 0.f, 0.f, 0.f);
            if (r0 + row < NN) v = __ldg((const float4*)(X + (size_t)(r0 + row) * 64) + c4);
            *(float4*)(sA + row * LDA + c4 * 4) = v;
        }
        loadW(Wres, 64);
        __syncthreads();
        mmaPhase(8);
#pragma unroll
        for (int n = 0; n < 8; n++)
            wmma::store_matrix_sync(sR + wid * 16 * LDA + n * 16, acc[n], LDA, wmma::mem_row_major);
        __syncthreads();
    }

    // ---- gather phase: sA[row] = X[node] + sum of neighbors ----
    {
        constexpr int F4 = K1 / 4;           // float4s per row: 16 or 32
        constexpr int RPI = 32 / F4;         // rows per warp-iter: 2 or 1
        int sub = (RPI == 2) ? (lane >> 4) : 0;
        int t = lane & (F4 - 1);
        for (int rr = sub; rr < 16; rr += RPI) {
            int row = wid * 16 + rr;
            int node = r0 + row;
            float4 a = make_float4(0.f, 0.f, 0.f, 0.f);
            if (node < NN) {
                if (L0) a = *(float4*)(sA + row * LDA + t * 4);   // raw x already staged
                else    a = __ldg((const float4*)(X + (size_t)node * K1) + t);
                int beg = __ldg(&g_rowstart[node]);
                int end = __ldg(&g_rowstart[node + 1]);
                int i = beg;
                for (; i + 4 <= end; i += 4) {
                    int s0 = __ldg(&g_csr[i + 0]);
                    int s1 = __ldg(&g_csr[i + 1]);
                    int s2 = __ldg(&g_csr[i + 2]);
                    int s3 = __ldg(&g_csr[i + 3]);
                    float4 v0 = __ldg((const float4*)(X + (size_t)s0 * K1) + t);
                    float4 v1 = __ldg((const float4*)(X + (size_t)s1 * K1) + t);
                    float4 v2 = __ldg((const float4*)(X + (size_t)s2 * K1) + t);
                    float4 v3 = __ldg((const float4*)(X + (size_t)s3 * K1) + t);
                    a.x += (v0.x + v1.x) + (v2.x + v3.x);
                    a.y += (v0.y + v1.y) + (v2.y + v3.y);
                    a.z += (v0.z + v1.z) + (v2.z + v3.z);
                    a.w += (v0.w + v1.w) + (v2.w + v3.w);
                }
                for (; i < end; i++) {
                    int s = __ldg(&g_csr[i]);
                    float4 v = __ldg((const float4*)(X + (size_t)s * K1) + t);
                    a.x += v.x; a.y += v.y; a.z += v.z; a.w += v.w;
                }
            }
            *(float4*)(sA + row * LDA + t * 4) = a;
        }
    }
    // ---- phase 1: T = relu(A @ W1 + b1) ----
    loadW(W1, K1);
    __syncthreads();
    mmaPhase(K1 / 8);
#pragma unroll
    for (int n = 0; n < 8; n++)
        wmma::store_matrix_sync(sA + wid * 16 * LDA + n * 16, acc[n], LDA, wmma::mem_row_major);
    __syncthreads();
    for (int idx = tid; idx < 128 * 128; idx += 256) {
        int row = idx >> 7, col = idx & 127;
        float* p = sA + row * LDA + col;
        *p = fmaxf(*p + __ldg(&b1[col]), 0.f);
    }
    __syncthreads();

    // ---- phase 2: D = T @ W2 ----
    loadW(W2, 128);
    __syncthreads();
    mmaPhase(16);
    __syncthreads();
#pragma unroll
    for (int n = 0; n < 8; n++)
        wmma::store_matrix_sync(sW + wid * 16 * LDA + n * 16, acc[n], LDA, wmma::mem_row_major);
    __syncthreads();

    // ---- epilogue: o = relu(D + b2 + Res); write h or pool ----
    for (int idx = tid; idx < 128 * 32; idx += 256) {
        int row = idx >> 5, c4 = idx & 31;
        int node = r0 + row;
        if (node >= NN) continue;
        float4 d = *(float4*)(sW + row * LDA + c4 * 4);
        float4 res4;
        if (L0) res4 = *(float4*)(sR + row * LDA + c4 * 4);
        else    res4 = __ldg((const float4*)(X + (size_t)node * HD) + c4);
        int col = c4 * 4;
        float4 o;
        o.x = fmaxf(d.x + __ldg(&b2[col + 0]) + res4.x, 0.f);
        o.y = fmaxf(d.y + __ldg(&b2[col + 1]) + res4.y, 0.f);
        o.z = fmaxf(d.z + __ldg(&b2[col + 2]) + res4.z, 0.f);
        o.w = fmaxf(d.w + __ldg(&b2[col + 3]) + res4.w, 0.f);
        if (POOL) {
            int b = __ldg(&g_batch[node]);
            float* p = g_sums + (size_t)b * HD + col;
            asm volatile("red.global.add.v4.f32 [%0], {%1,%2,%3,%4};"
                         :: "l"(p), "f"(o.x), "f"(o.y), "f"(o.z), "f"(o.w) : "memory");
        } else {
            *((float4*)(OutH + (size_t)node * HD) + c4) = o;
        }
    }
}

// ============================================================
// pooling prep + head
// ============================================================
__global__ void zero_pool() {
    int i = blockIdx.x * blockDim.x + threadIdx.x;
    if (i < NG * HD) g_sums[i] = 0.f;
    if (i < NG) g_cnt[i] = 0.f;
}
__global__ void pool_cnt() {
    int i = blockIdx.x * blockDim.x + threadIdx.x;
    if (i < NN) atomicAdd(&g_cnt[g_batch[i]], 1.0f);
}
__global__ void __launch_bounds__(128)
head_kernel(const float* __restrict__ fW1, const float* __restrict__ fb1,
            const float* __restrict__ fW2, const float* __restrict__ fb2,
            float* __restrict__ out) {
    int g = blockIdx.x;
    int t = threadIdx.x;
    __shared__ float sp[HD];
    __shared__ float red[HD];
    float inv = 1.0f / fmaxf(g_cnt[g], 1.0f);
    sp[t] = g_sums[(size_t)g * HD + t] * inv;
    __syncthreads();
    float acc = 0.f;
#pragma unroll 8
    for (int k = 0; k < HD; k++) acc = fmaf(sp[k], __ldg(&fW1[(size_t)k * HD + t]), acc);
    float hh = acc + __ldg(&fb1[t]);
    hh = (hh > 0.f) ? hh : hh * SLOPE;
    red[t] = hh * __ldg(&fW2[t]);
    __syncthreads();
    for (int s = 64; s > 0; s >>= 1) {
        if (t < s) red[t] += red[t + s];
        __syncthreads();
    }
    if (t == 0) out[g] = red[0] + __ldg(&fb2[0]);
}

// ============================================================
// launch
// ============================================================
extern "C" void kernel_launch(void* const* d_in, const int* in_sizes, int n_in,
                              void* d_out, int out_size) {
    const float* x     = (const float*)d_in[0];
    const void*  ei    = d_in[1];
    const void*  batch = d_in[2];
    const float* l0_W1   = (const float*)d_in[3];
    const float* l0_b1   = (const float*)d_in[4];
    const float* l0_W2   = (const float*)d_in[5];
    const float* l0_b2   = (const float*)d_in[6];
    const float* l0_Wres = (const float*)d_in[7];
    const float* Ws1 = (const float*)d_in[8];
    const float* bs1 = (const float*)d_in[9];
    const float* Ws2 = (const float*)d_in[10];
    const float* bs2 = (const float*)d_in[11];
    const float* fW1 = (const float*)d_in[12];
    const float* fb1 = (const float*)d_in[13];
    const float* fW2 = (const float*)d_in[14];
    const float* fb2 = (const float*)d_in[15];
    float* out = (float*)d_out;

    float *h0, *h1;
    int *eiI, *batchI;
    cudaGetSymbolAddress((void**)&h0, g_h0);
    cudaGetSymbolAddress((void**)&h1, g_h1);
    cudaGetSymbolAddress((void**)&eiI, g_ei);
    cudaGetSymbolAddress((void**)&batchI, g_batch);

    const int DSM_L0 = 3 * 128 * LDA * 4;   // 202752
    const int DSM    = 2 * 128 * LDA * 4;   // 135168
    static bool attr_set = false;
    if (!attr_set) {
        cudaFuncSetAttribute(gin_fused<64, true, false>,   cudaFuncAttributeMaxDynamicSharedMemorySize, DSM_L0);
        cudaFuncSetAttribute(gin_fused<128, false, false>, cudaFuncAttributeMaxDynamicSharedMemorySize, DSM);
        cudaFuncSetAttribute(gin_fused<128, false, true>,  cudaFuncAttributeMaxDynamicSharedMemorySize, DSM);
        attr_set = true;
    }

    // ---- index conversion + CSR build ----
    detect_dtype<<<1, 256>>>((const int*)ei);
    convert_idx<<<(2 * NE + 255) / 256, 256>>>(ei, eiI, 2 * NE);
    convert_idx<<<(NN + 255) / 256, 256>>>(batch, batchI, NN);
    zero_deg<<<(NN + 255) / 256, 256>>>();
    hist_dst<<<(NE + 255) / 256, 256>>>();
    scan_deg<<<1, 1024>>>();
    fill_csr<<<(NE + 255) / 256, 256>>>();

    const int blocks = (NN + 127) / 128;  // 391

    // ---- layers (aggregation fused into each) ----
    gin_fused<64, true, false><<<blocks, 256, DSM_L0>>>(
        x, l0_W1, l0_b1, l0_W2, l0_b2, l0_Wres, h0);
    gin_fused<128, false, false><<<blocks, 256, DSM>>>(
        h0, Ws1, bs1, Ws2, bs2, nullptr, h1);
    gin_fused<128, false, false><<<blocks, 256, DSM>>>(
        h1, Ws1 + (size_t)HD * HD, bs1 + HD, Ws2 + (size_t)HD * HD, bs2 + HD, nullptr, h0);
    zero_pool<<<(NG * HD + 255) / 256, 256>>>();
    pool_cnt<<<(NN + 255) / 256, 256>>>();
    gin_fused<128, false, true><<<blocks, 256, DSM>>>(
        h0, Ws1 + (size_t)2 * HD * HD, bs1 + 2 * HD, Ws2 + (size_t)2 * HD * HD, bs2 + 2 * HD, nullptr, nullptr);

    // ---- head ----
    head_kernel<<<NG, 128>>>(fW1, fb1, fW2, fb2, out);
}

// round 7
// speedup vs baseline: 1.2410x; 1.2410x over previous
#include <cuda_runtime.h>
#include <mma.h>
#include <cstdint>

using namespace nvcuda;

// ---------------- problem constants ----------------
constexpr int NN = 50000;
constexpr int NE = 800000;
constexpr int IND = 64;
constexpr int HD = 128;
constexpr int NG = 1024;
constexpr float SLOPE = 0.01f;

constexpr int LDA = 132;   // smem leading dim

// ---------------- scratch (device globals) ----------------
__device__ __align__(256) float g_agg[(size_t)NN * HD];
__device__ __align__(256) float g_h0[(size_t)NN * HD];
__device__ __align__(256) float g_h1[(size_t)NN * HD];
__device__ __align__(256) float g_sums[(size_t)NG * HD];
__device__ __align__(256) float g_cnt[NG];
__device__ __align__(256) int   g_ei[2 * NE];
__device__ __align__(256) int   g_batch[NN];
__device__ __align__(256) int   g_deg[NN];
__device__ __align__(256) int   g_cur[NN];
__device__ __align__(256) int   g_rowstart[NN + 1];
__device__ __align__(256) int   g_csr[NE];
__device__ int g_is64;

// ============================================================
// index dtype detection + conversion
// ============================================================
__global__ void detect_dtype(const int* __restrict__ raw) {
    __shared__ int s_any;
    if (threadIdx.x == 0) s_any = 0;
    __syncthreads();
    int bad = 0;
    for (int i = threadIdx.x; i < 4096; i += blockDim.x) bad |= raw[2 * i + 1];
    if (bad) atomicOr(&s_any, 1);
    __syncthreads();
    if (threadIdx.x == 0) g_is64 = (s_any == 0) ? 1 : 0;
}
__global__ void convert_idx(const void* __restrict__ raw, int* __restrict__ out, int n) {
    int i = blockIdx.x * blockDim.x + threadIdx.x;
    if (i >= n) return;
    if (g_is64) out[i] = (int)((const long long*)raw)[i];
    else        out[i] = ((const int*)raw)[i];
}

// ============================================================
// CSR build: histogram -> scan -> fill
// ============================================================
__global__ void zero_deg() {
    int i = blockIdx.x * blockDim.x + threadIdx.x;
    if (i < NN) g_deg[i] = 0;
}
__global__ void hist_dst() {
    int e = blockIdx.x * blockDim.x + threadIdx.x;
    if (e < NE) atomicAdd(&g_deg[g_ei[NE + e]], 1);
}
__global__ void __launch_bounds__(1024) scan_deg() {
    __shared__ int part[1024];
    int tid = threadIdx.x;
    const int CH = (NN + 1023) / 1024;  // 49
    int base = tid * CH;
    int s = 0;
    for (int i = 0; i < CH; i++) {
        int idx = base + i;
        if (idx < NN) s += g_deg[idx];
    }
    part[tid] = s;
    __syncthreads();
    for (int off = 1; off < 1024; off <<= 1) {
        int v = (tid >= off) ? part[tid - off] : 0;
        __syncthreads();
        part[tid] += v;
        __syncthreads();
    }
    int run = (tid > 0) ? part[tid - 1] : 0;
    for (int i = 0; i < CH; i++) {
        int idx = base + i;
        if (idx < NN) {
            int d = g_deg[idx];
            g_rowstart[idx] = run;
            run += d;
        }
    }
    if (tid == 1023) g_rowstart[NN] = run;
    for (int i = tid; i < NN; i += 1024) g_cur[i] = 0;
}
__global__ void fill_csr() {
    int e = blockIdx.x * blockDim.x + threadIdx.x;
    if (e >= NE) return;
    int s = g_ei[e];
    int d = g_ei[NE + e];
    int p = atomicAdd(&g_cur[d], 1);
    g_csr[g_rowstart[d] + p] = s;
}

// ============================================================
// CSR gather: agg[node] = X[node] + sum_{src in csr[node]} X[src]
// D=128: one warp per node (lane = float4 chunk, 32 chunks)
// D=64 : half-warp per node (16 chunks)
// Coalesced full-row loads, 2-way unrolled independent neighbor loads.
// ============================================================
template<int D>
__global__ void __launch_bounds__(256)
gather_agg(const float* __restrict__ X) {
    constexpr int F4 = D / 4;                 // 32 or 16
    constexpr int NPW = 32 / F4;              // nodes per warp: 1 or 2
    int tid = blockIdx.x * blockDim.x + threadIdx.x;
    int gw = tid >> 5;                        // global warp
    int lane = tid & 31;
    int node = gw * NPW + (NPW == 2 ? (lane >> 4) : 0);
    int t = lane & (F4 - 1);
    if (node >= NN) return;

    float4 a = __ldg((const float4*)(X + (size_t)node * D) + t);
    int beg = __ldg(&g_rowstart[node]);
    int end = __ldg(&g_rowstart[node + 1]);
    int i = beg;
    for (; i + 2 <= end; i += 2) {
        int s0 = __ldg(&g_csr[i + 0]);
        int s1 = __ldg(&g_csr[i + 1]);
        float4 v0 = __ldg((const float4*)(X + (size_t)s0 * D) + t);
        float4 v1 = __ldg((const float4*)(X + (size_t)s1 * D) + t);
        a.x += v0.x + v1.x;
        a.y += v0.y + v1.y;
        a.z += v0.z + v1.z;
        a.w += v0.w + v1.w;
    }
    if (i < end) {
        int s = __ldg(&g_csr[i]);
        float4 v = __ldg((const float4*)(X + (size_t)s * D) + t);
        a.x += v.x; a.y += v.y; a.z += v.z; a.w += v.w;
    }
    *((float4*)(g_agg + (size_t)node * D) + t) = a;
}

// ============================================================
// GIN MLP on warp tensor cores (wmma tf32):
//   Out = relu( relu(A@W1 + b1) @ W2 + b2 + Res )
// L0: Res = x @ Wres computed on-chip into sR; else Res = XRes.
// POOL: epilogue accumulates graph sums instead of writing h.
// ============================================================
template<int K1, bool L0, bool POOL>
__global__ void __launch_bounds__(256)
gin_wmma(const float* __restrict__ A,
         const float* __restrict__ W1, const float* __restrict__ b1,
         const float* __restrict__ W2, const float* __restrict__ b2,
         const float* __restrict__ Wres,
         const float* __restrict__ XRes,   // L0: x ; else residual source
         float* __restrict__ Out) {
    extern __shared__ float sm[];
    float* sA = sm;                     // 128 x LDA
    float* sW = sm + 128 * LDA;         // 128 x LDA
    float* sR = sm + 2 * 128 * LDA;     // 128 x LDA (L0 only)

    int tid = threadIdx.x;
    int wid = tid >> 5;
    int r0 = blockIdx.x * 128;

    wmma::fragment<wmma::accumulator, 16, 16, 8, float> acc[8];

    auto loadA = [&](const float* __restrict__ src, int K) {
        int n4 = 128 * (K >> 2);
        int c4n = K >> 2;
        for (int idx = tid; idx < n4; idx += 256) {
            int row = idx / c4n, c4 = idx % c4n;
            float4 v = make_float4(0.f, 0.f, 0.f, 0.f);
            if (r0 + row < NN) v = __ldg((const float4*)(src + (size_t)(r0 + row) * K) + c4);
            *(float4*)(sA + row * LDA + c4 * 4) = v;
        }
    };
    auto loadW = [&](const float* __restrict__ src, int K) {
        int n4 = K * 32;
        for (int idx = tid; idx < n4; idx += 256) {
            int row = idx >> 5, c4 = idx & 31;
            float4 v = __ldg((const float4*)(src + (size_t)row * 128) + c4);
            *(float4*)(sW + row * LDA + c4 * 4) = v;
        }
    };
    auto mmaPhase = [&](int ksteps) {
#pragma unroll
        for (int n = 0; n < 8; n++) wmma::fill_fragment(acc[n], 0.f);
        for (int k = 0; k < ksteps; k++) {
            wmma::fragment<wmma::matrix_a, 16, 16, 8, wmma::precision::tf32, wmma::row_major> af;
            wmma::load_matrix_sync(af, sA + wid * 16 * LDA + k * 8, LDA);
#pragma unroll
            for (int i = 0; i < af.num_elements; i++) af.x[i] = wmma::__float_to_tf32(af.x[i]);
#pragma unroll
            for (int n = 0; n < 8; n++) {
                wmma::fragment<wmma::matrix_b, 16, 16, 8, wmma::precision::tf32, wmma::row_major> bf;
                wmma::load_matrix_sync(bf, sW + k * 8 * LDA + n * 16, LDA);
#pragma unroll
                for (int i = 0; i < bf.num_elements; i++) bf.x[i] = wmma::__float_to_tf32(bf.x[i]);
                wmma::mma_sync(acc[n], af, bf, acc[n]);
            }
        }
    };

    // ---- L0: residual projection R = x @ Wres -> sR ----
    if (L0) {
        loadA(XRes, 64);
        loadW(Wres, 64);
        __syncthreads();
        mmaPhase(8);
#pragma unroll
        for (int n = 0; n < 8; n++)
            wmma::store_matrix_sync(sR + wid * 16 * LDA + n * 16, acc[n], LDA, wmma::mem_row_major);
        __syncthreads();
    }

    // ---- phase 1: T = relu(A @ W1 + b1) ----
    loadA(A, K1);
    loadW(W1, K1);
    __syncthreads();
    mmaPhase(K1 / 8);
#pragma unroll
    for (int n = 0; n < 8; n++)
        wmma::store_matrix_sync(sA + wid * 16 * LDA + n * 16, acc[n], LDA, wmma::mem_row_major);
    __syncthreads();
    for (int idx = tid; idx < 128 * 128; idx += 256) {
        int row = idx >> 7, col = idx & 127;
        float* p = sA + row * LDA + col;
        *p = fmaxf(*p + __ldg(&b1[col]), 0.f);
    }
    __syncthreads();

    // ---- phase 2: D = T @ W2 ----
    loadW(W2, 128);
    __syncthreads();
    mmaPhase(16);
    __syncthreads();
#pragma unroll
    for (int n = 0; n < 8; n++)
        wmma::store_matrix_sync(sW + wid * 16 * LDA + n * 16, acc[n], LDA, wmma::mem_row_major);
    __syncthreads();

    // ---- epilogue ----
    for (int idx = tid; idx < 128 * 32; idx += 256) {
        int row = idx >> 5, c4 = idx & 31;
        int node = r0 + row;
        if (node >= NN) continue;
        float4 d = *(float4*)(sW + row * LDA + c4 * 4);
        float4 res4;
        if (L0) res4 = *(float4*)(sR + row * LDA + c4 * 4);
        else    res4 = __ldg((const float4*)(XRes + (size_t)node * HD) + c4);
        int col = c4 * 4;
        float4 o;
        o.x = fmaxf(d.x + __ldg(&b2[col + 0]) + res4.x, 0.f);
        o.y = fmaxf(d.y + __ldg(&b2[col + 1]) + res4.y, 0.f);
        o.z = fmaxf(d.z + __ldg(&b2[col + 2]) + res4.z, 0.f);
        o.w = fmaxf(d.w + __ldg(&b2[col + 3]) + res4.w, 0.f);
        if (POOL) {
            int b = __ldg(&g_batch[node]);
            float* p = g_sums + (size_t)b * HD + col;
            asm volatile("red.global.add.v4.f32 [%0], {%1,%2,%3,%4};"
                         :: "l"(p), "f"(o.x), "f"(o.y), "f"(o.z), "f"(o.w) : "memory");
        } else {
            *((float4*)(Out + (size_t)node * HD) + c4) = o;
        }
    }
}

// ============================================================
// pooling prep + head
// ============================================================
__global__ void zero_pool() {
    int i = blockIdx.x * blockDim.x + threadIdx.x;
    if (i < NG * HD) g_sums[i] = 0.f;
    if (i < NG) g_cnt[i] = 0.f;
}
__global__ void pool_cnt() {
    int i = blockIdx.x * blockDim.x + threadIdx.x;
    if (i < NN) atomicAdd(&g_cnt[g_batch[i]], 1.0f);
}
__global__ void __launch_bounds__(128)
head_kernel(const float* __restrict__ fW1, const float* __restrict__ fb1,
            const float* __restrict__ fW2, const float* __restrict__ fb2,
            float* __restrict__ out) {
    int g = blockIdx.x;
    int t = threadIdx.x;
    __shared__ float sp[HD];
    __shared__ float red[HD];
    float inv = 1.0f / fmaxf(g_cnt[g], 1.0f);
    sp[t] = g_sums[(size_t)g * HD + t] * inv;
    __syncthreads();
    float acc = 0.f;
#pragma unroll 8
    for (int k = 0; k < HD; k++) acc = fmaf(sp[k], __ldg(&fW1[(size_t)k * HD + t]), acc);
    float hh = acc + __ldg(&fb1[t]);
    hh = (hh > 0.f) ? hh : hh * SLOPE;
    red[t] = hh * __ldg(&fW2[t]);
    __syncthreads();
    for (int s = 64; s > 0; s >>= 1) {
        if (t < s) red[t] += red[t + s];
        __syncthreads();
    }
    if (t == 0) out[g] = red[0] + __ldg(&fb2[0]);
}

// ============================================================
// launch
// ============================================================
extern "C" void kernel_launch(void* const* d_in, const int* in_sizes, int n_in,
                              void* d_out, int out_size) {
    const float* x     = (const float*)d_in[0];
    const void*  ei    = d_in[1];
    const void*  batch = d_in[2];
    const float* l0_W1   = (const float*)d_in[3];
    const float* l0_b1   = (const float*)d_in[4];
    const float* l0_W2   = (const float*)d_in[5];
    const float* l0_b2   = (const float*)d_in[6];
    const float* l0_Wres = (const float*)d_in[7];
    const float* Ws1 = (const float*)d_in[8];
    const float* bs1 = (const float*)d_in[9];
    const float* Ws2 = (const float*)d_in[10];
    const float* bs2 = (const float*)d_in[11];
    const float* fW1 = (const float*)d_in[12];
    const float* fb1 = (const float*)d_in[13];
    const float* fW2 = (const float*)d_in[14];
    const float* fb2 = (const float*)d_in[15];
    float* out = (float*)d_out;

    float *agg, *h0, *h1;
    int *eiI, *batchI;
    cudaGetSymbolAddress((void**)&agg, g_agg);
    cudaGetSymbolAddress((void**)&h0, g_h0);
    cudaGetSymbolAddress((void**)&h1, g_h1);
    cudaGetSymbolAddress((void**)&eiI, g_ei);
    cudaGetSymbolAddress((void**)&batchI, g_batch);

    const int DSM_L0 = 3 * 128 * LDA * 4;   // 202752
    const int DSM    = 2 * 128 * LDA * 4;   // 135168
    static bool attr_set = false;
    if (!attr_set) {
        cudaFuncSetAttribute(gin_wmma<64, true, false>,   cudaFuncAttributeMaxDynamicSharedMemorySize, DSM_L0);
        cudaFuncSetAttribute(gin_wmma<128, false, false>, cudaFuncAttributeMaxDynamicSharedMemorySize, DSM);
        cudaFuncSetAttribute(gin_wmma<128, false, true>,  cudaFuncAttributeMaxDynamicSharedMemorySize, DSM);
        attr_set = true;
    }

    // ---- index conversion + CSR build ----
    detect_dtype<<<1, 256>>>((const int*)ei);
    convert_idx<<<(2 * NE + 255) / 256, 256>>>(ei, eiI, 2 * NE);
    convert_idx<<<(NN + 255) / 256, 256>>>(batch, batchI, NN);
    zero_deg<<<(NN + 255) / 256, 256>>>();
    hist_dst<<<(NE + 255) / 256, 256>>>();
    scan_deg<<<1, 1024>>>();
    fill_csr<<<(NE + 255) / 256, 256>>>();

    const int blocks = (NN + 127) / 128;                  // 391
    const int gblk64 = (NN / 2 * 32 + 255) / 256;         // half-warp per node
    const int gblk128 = (NN * 32 + 255) / 256;            // warp per node

    // ---- layer 0 (64 -> 128, on-chip residual projection) ----
    gather_agg<IND><<<gblk64 + 1, 256>>>(x);
    gin_wmma<64, true, false><<<blocks, 256, DSM_L0>>>(
        agg, l0_W1, l0_b1, l0_W2, l0_b2, l0_Wres, x, h0);

    // ---- layers 1..3 ----
    zero_pool<<<(NG * HD + 255) / 256, 256>>>();
    pool_cnt<<<(NN + 255) / 256, 256>>>();

    gather_agg<HD><<<gblk128, 256>>>(h0);
    gin_wmma<128, false, false><<<blocks, 256, DSM>>>(
        agg, Ws1, bs1, Ws2, bs2, nullptr, h0, h1);

    gather_agg<HD><<<gblk128, 256>>>(h1);
    gin_wmma<128, false, false><<<blocks, 256, DSM>>>(
        agg, Ws1 + (size_t)HD * HD, bs1 + HD, Ws2 + (size_t)HD * HD, bs2 + HD, nullptr, h1, h0);

    gather_agg<HD><<<gblk128, 256>>>(h0);
    gin_wmma<128, false, true><<<blocks, 256, DSM>>>(
        agg, Ws1 + (size_t)2 * HD * HD, bs1 + 2 * HD, Ws2 + (size_t)2 * HD * HD, bs2 + 2 * HD, nullptr, h0, nullptr);

    // ---- head ----
    head_kernel<<<NG, 128>>>(fW1, fb1, fW2, fb2, out);
}

// round 8
// speedup vs baseline: 2.0768x; 1.6735x over previous
#include <cuda_runtime.h>
#include <cuda_fp16.h>
#include <mma.h>
#include <cstdint>

using namespace nvcuda;

// ---------------- problem constants ----------------
constexpr int NN = 50000;
constexpr int NE = 800000;
constexpr int IND = 64;
constexpr int HD = 128;
constexpr int NG = 1024;
constexpr float SLOPE = 0.01f;

constexpr int LDH = 136;   // half smem leading dim (17x16B rows)
constexpr int LDF = 132;   // float smem leading dim

// ---------------- scratch (device globals) ----------------
__device__ __align__(256) __half g_agg[(size_t)NN * HD];
__device__ __align__(256) __half g_h0[(size_t)NN * HD];
__device__ __align__(256) __half g_h1[(size_t)NN * HD];
__device__ __align__(256) float g_sums[(size_t)NG * HD];
__device__ __align__(256) float g_cnt[NG];
__device__ __align__(256) int   g_ei[2 * NE];
__device__ __align__(256) int   g_batch[NN];
__device__ __align__(256) int   g_deg[NN];
__device__ __align__(256) int   g_cur[NN];
__device__ __align__(256) int   g_rowstart[NN + 1];
__device__ __align__(256) int   g_csr[NE];
__device__ int g_is64;

// ============================================================
// index dtype detection + conversion
// ============================================================
__global__ void detect_dtype(const int* __restrict__ raw) {
    __shared__ int s_any;
    if (threadIdx.x == 0) s_any = 0;
    __syncthreads();
    int bad = 0;
    for (int i = threadIdx.x; i < 4096; i += blockDim.x) bad |= raw[2 * i + 1];
    if (bad) atomicOr(&s_any, 1);
    __syncthreads();
    if (threadIdx.x == 0) g_is64 = (s_any == 0) ? 1 : 0;
}
__global__ void convert_idx(const void* __restrict__ raw, int* __restrict__ out, int n) {
    int i = blockIdx.x * blockDim.x + threadIdx.x;
    if (i >= n) return;
    if (g_is64) out[i] = (int)((const long long*)raw)[i];
    else        out[i] = ((const int*)raw)[i];
}

// ============================================================
// CSR build: histogram -> scan -> fill
// ============================================================
__global__ void zero_deg() {
    int i = blockIdx.x * blockDim.x + threadIdx.x;
    if (i < NN) g_deg[i] = 0;
}
__global__ void hist_dst() {
    int e = blockIdx.x * blockDim.x + threadIdx.x;
    if (e < NE) atomicAdd(&g_deg[g_ei[NE + e]], 1);
}
__global__ void __launch_bounds__(1024) scan_deg() {
    __shared__ int part[1024];
    int tid = threadIdx.x;
    const int CH = (NN + 1023) / 1024;
    int base = tid * CH;
    int s = 0;
    for (int i = 0; i < CH; i++) {
        int idx = base + i;
        if (idx < NN) s += g_deg[idx];
    }
    part[tid] = s;
    __syncthreads();
    for (int off = 1; off < 1024; off <<= 1) {
        int v = (tid >= off) ? part[tid - off] : 0;
        __syncthreads();
        part[tid] += v;
        __syncthreads();
    }
    int run = (tid > 0) ? part[tid - 1] : 0;
    for (int i = 0; i < CH; i++) {
        int idx = base + i;
        if (idx < NN) {
            int d = g_deg[idx];
            g_rowstart[idx] = run;
            run += d;
        }
    }
    if (tid == 1023) g_rowstart[NN] = run;
    for (int i = tid; i < NN; i += 1024) g_cur[i] = 0;
}
__global__ void fill_csr() {
    int e = blockIdx.x * blockDim.x + threadIdx.x;
    if (e >= NE) return;
    int s = g_ei[e];
    int d = g_ei[NE + e];
    int p = atomicAdd(&g_cur[d], 1);
    g_csr[g_rowstart[d] + p] = s;
}

// ============================================================
// gathers: agg[node] = X[node] + sum_{src in csr[node]} X[src]
// fp32 accumulate, fp16 output. Half-warp per node (16 chunks).
// ============================================================
// L0: X fp32, D=64. chunk = float4 (4 floats), 16 chunks/row.
__global__ void __launch_bounds__(256)
gather_f32(const float* __restrict__ X) {
    int tid = blockIdx.x * blockDim.x + threadIdx.x;
    int node = tid >> 4;
    int t = tid & 15;
    if (node >= NN) return;
    float4 a = __ldg((const float4*)(X + (size_t)node * 64) + t);
    int beg = __ldg(&g_rowstart[node]);
    int end = __ldg(&g_rowstart[node + 1]);
    int i = beg;
    for (; i + 2 <= end; i += 2) {
        int s0 = __ldg(&g_csr[i + 0]);
        int s1 = __ldg(&g_csr[i + 1]);
        float4 v0 = __ldg((const float4*)(X + (size_t)s0 * 64) + t);
        float4 v1 = __ldg((const float4*)(X + (size_t)s1 * 64) + t);
        a.x += v0.x + v1.x; a.y += v0.y + v1.y;
        a.z += v0.z + v1.z; a.w += v0.w + v1.w;
    }
    if (i < end) {
        int s = __ldg(&g_csr[i]);
        float4 v = __ldg((const float4*)(X + (size_t)s * 64) + t);
        a.x += v.x; a.y += v.y; a.z += v.z; a.w += v.w;
    }
    __half2* o = (__half2*)(g_agg + (size_t)node * 64 + t * 4);
    o[0] = __floats2half2_rn(a.x, a.y);
    o[1] = __floats2half2_rn(a.z, a.w);
}

// layers 1..3: X fp16, D=128. chunk = uint4 (8 halves), 16 chunks/row.
__global__ void __launch_bounds__(256)
gather_f16(const __half* __restrict__ X) {
    int tid = blockIdx.x * blockDim.x + threadIdx.x;
    int node = tid >> 4;
    int t = tid & 15;
    if (node >= NN) return;
    const uint4* Xr = (const uint4*)X;
    float2 a[4];
    {
        uint4 v = __ldg(Xr + (size_t)node * 16 + t);
        const __half2* h = (const __half2*)&v;
#pragma unroll
        for (int q = 0; q < 4; q++) a[q] = __half22float2(h[q]);
    }
    int beg = __ldg(&g_rowstart[node]);
    int end = __ldg(&g_rowstart[node + 1]);
    int i = beg;
    for (; i + 2 <= end; i += 2) {
        int s0 = __ldg(&g_csr[i + 0]);
        int s1 = __ldg(&g_csr[i + 1]);
        uint4 v0 = __ldg(Xr + (size_t)s0 * 16 + t);
        uint4 v1 = __ldg(Xr + (size_t)s1 * 16 + t);
        const __half2* h0 = (const __half2*)&v0;
        const __half2* h1 = (const __half2*)&v1;
#pragma unroll
        for (int q = 0; q < 4; q++) {
            float2 f0 = __half22float2(h0[q]);
            float2 f1 = __half22float2(h1[q]);
            a[q].x += f0.x + f1.x;
            a[q].y += f0.y + f1.y;
        }
    }
    if (i < end) {
        int s = __ldg(&g_csr[i]);
        uint4 v = __ldg(Xr + (size_t)s * 16 + t);
        const __half2* h = (const __half2*)&v;
#pragma unroll
        for (int q = 0; q < 4; q++) {
            float2 f = __half22float2(h[q]);
            a[q].x += f.x;
            a[q].y += f.y;
        }
    }
    uint4 o;
    __half2* oh = (__half2*)&o;
#pragma unroll
    for (int q = 0; q < 4; q++) oh[q] = __floats2half2_rn(a[q].x, a[q].y);
    ((uint4*)g_agg)[(size_t)node * 16 + t] = o;
}

// ============================================================
// GIN MLP on fp16 tensor cores (wmma m16n16k16, fp32 accum):
//   Out = relu( relu(A@W1 + b1) @ W2 + b2 + Res )
// L0: Res = x @ Wres computed on-chip (float, sR); else Res = XRes (half).
// POOL: epilogue pools fp32 into g_sums instead of writing h.
// Block: 256 threads = 8 warps; warp w owns rows [16w, 16w+16).
// ============================================================
template<int K1, bool L0, bool POOL>
__global__ void __launch_bounds__(256)
gin_wmma(const __half* __restrict__ A,
         const float* __restrict__ W1, const float* __restrict__ b1,
         const float* __restrict__ W2, const float* __restrict__ b2,
         const float* __restrict__ Wres,
         const float* __restrict__ Xf,      // L0 only: raw x (fp32)
         const __half* __restrict__ XRes,   // layers 1..3: residual source
         __half* __restrict__ Out) {
    extern __shared__ char smc[];
    __half* sAh = (__half*)smc;                      // 128 x LDH half
    __half* sWh = (__half*)(smc + 34816);            // 128 x LDH half
    float*  sD  = (float*)(smc + 69632);             // 128 x LDF float
    float*  sR  = (float*)(smc + 137216);            // 128 x LDF float (L0)

    int tid = threadIdx.x;
    int wid = tid >> 5;
    int r0 = blockIdx.x * 128;

    wmma::fragment<wmma::accumulator, 16, 16, 16, float> acc[8];

    // A tile from half source (8 halves per uint4 chunk)
    auto loadA_h = [&](const __half* __restrict__ src, int K) {
        int cn = K >> 3;
        int n = 128 * cn;
        for (int idx = tid; idx < n; idx += 256) {
            int row = idx / cn, c = idx % cn;
            uint4 v = make_uint4(0, 0, 0, 0);
            if (r0 + row < NN) v = __ldg((const uint4*)src + (size_t)(r0 + row) * cn + c);
            *(uint4*)(sAh + row * LDH + c * 8) = v;
        }
    };
    // A tile from fp32 source (L0 x), converted to half
    auto loadA_f = [&]() {
        for (int idx = tid; idx < 128 * 16; idx += 256) {
            int row = idx >> 4, c4 = idx & 15;
            float4 v = make_float4(0.f, 0.f, 0.f, 0.f);
            if (r0 + row < NN) v = __ldg((const float4*)(Xf + (size_t)(r0 + row) * 64) + c4);
            __half2* o = (__half2*)(sAh + row * LDH + c4 * 4);
            o[0] = __floats2half2_rn(v.x, v.y);
            o[1] = __floats2half2_rn(v.z, v.w);
        }
    };
    // W tile: fp32 [K][128] -> half smem
    auto loadW = [&](const float* __restrict__ src, int K) {
        int n = K * 32;
        for (int idx = tid; idx < n; idx += 256) {
            int row = idx >> 5, c4 = idx & 31;
            float4 v = __ldg((const float4*)(src + (size_t)row * 128) + c4);
            __half2* o = (__half2*)(sWh + row * LDH + c4 * 4);
            o[0] = __floats2half2_rn(v.x, v.y);
            o[1] = __floats2half2_rn(v.z, v.w);
        }
    };
    auto mmaPhase = [&](int ksteps) {
#pragma unroll
        for (int n = 0; n < 8; n++) wmma::fill_fragment(acc[n], 0.f);
        for (int k = 0; k < ksteps; k++) {
            wmma::fragment<wmma::matrix_a, 16, 16, 16, __half, wmma::row_major> af;
            wmma::load_matrix_sync(af, sAh + wid * 16 * LDH + k * 16, LDH);
#pragma unroll
            for (int n = 0; n < 8; n++) {
                wmma::fragment<wmma::matrix_b, 16, 16, 16, __half, wmma::row_major> bf;
                wmma::load_matrix_sync(bf, sWh + k * 16 * LDH + n * 16, LDH);
                wmma::mma_sync(acc[n], af, bf, acc[n]);
            }
        }
    };

    // ---- L0: residual projection R = x @ Wres -> sR (float) ----
    if (L0) {
        loadA_f();
        loadW(Wres, 64);
        __syncthreads();
        mmaPhase(4);
#pragma unroll
        for (int n = 0; n < 8; n++)
            wmma::store_matrix_sync(sR + wid * 16 * LDF + n * 16, acc[n], LDF, wmma::mem_row_major);
        __syncthreads();
    }

    // ---- phase 1: T = relu(A @ W1 + b1) ----
    loadA_h(A, K1);
    loadW(W1, K1);
    __syncthreads();
    mmaPhase(K1 / 16);
#pragma unroll
    for (int n = 0; n < 8; n++)
        wmma::store_matrix_sync(sD + wid * 16 * LDF + n * 16, acc[n], LDF, wmma::mem_row_major);
    __syncthreads();
    for (int idx = tid; idx < 128 * 128; idx += 256) {
        int row = idx >> 7, col = idx & 127;
        float v = fmaxf(sD[row * LDF + col] + __ldg(&b1[col]), 0.f);
        sAh[row * LDH + col] = __float2half_rn(v);
    }
    __syncthreads();

    // ---- phase 2: D = T @ W2 ----
    loadW(W2, 128);
    __syncthreads();
    mmaPhase(8);
    __syncthreads();
#pragma unroll
    for (int n = 0; n < 8; n++)
        wmma::store_matrix_sync(sD + wid * 16 * LDF + n * 16, acc[n], LDF, wmma::mem_row_major);
    __syncthreads();

    // ---- epilogue: o = relu(D + b2 + Res) ----
    for (int idx = tid; idx < 128 * 32; idx += 256) {
        int row = idx >> 5, c4 = idx & 31;
        int node = r0 + row;
        if (node >= NN) continue;
        float4 d = *(float4*)(sD + row * LDF + c4 * 4);
        float4 res4;
        if (L0) {
            res4 = *(float4*)(sR + row * LDF + c4 * 4);
        } else {
            uint2 rv = __ldg((const uint2*)(XRes + (size_t)node * HD + c4 * 4));
            const __half2* rh = (const __half2*)&rv;
            float2 r01 = __half22float2(rh[0]);
            float2 r23 = __half22float2(rh[1]);
            res4 = make_float4(r01.x, r01.y, r23.x, r23.y);
        }
        int col = c4 * 4;
        float4 o;
        o.x = fmaxf(d.x + __ldg(&b2[col + 0]) + res4.x, 0.f);
        o.y = fmaxf(d.y + __ldg(&b2[col + 1]) + res4.y, 0.f);
        o.z = fmaxf(d.z + __ldg(&b2[col + 2]) + res4.z, 0.f);
        o.w = fmaxf(d.w + __ldg(&b2[col + 3]) + res4.w, 0.f);
        if (POOL) {
            int b = __ldg(&g_batch[node]);
            float* p = g_sums + (size_t)b * HD + col;
            asm volatile("red.global.add.v4.f32 [%0], {%1,%2,%3,%4};"
                         :: "l"(p), "f"(o.x), "f"(o.y), "f"(o.z), "f"(o.w) : "memory");
        } else {
            uint2 ov;
            __half2* oh = (__half2*)&ov;
            oh[0] = __floats2half2_rn(o.x, o.y);
            oh[1] = __floats2half2_rn(o.z, o.w);
            *(uint2*)(Out + (size_t)node * HD + col) = ov;
        }
    }
}

// ============================================================
// pooling prep + head
// ============================================================
__global__ void zero_pool() {
    int i = blockIdx.x * blockDim.x + threadIdx.x;
    if (i < NG * HD) g_sums[i] = 0.f;
    if (i < NG) g_cnt[i] = 0.f;
}
__global__ void pool_cnt() {
    int i = blockIdx.x * blockDim.x + threadIdx.x;
    if (i < NN) atomicAdd(&g_cnt[g_batch[i]], 1.0f);
}
__global__ void __launch_bounds__(128)
head_kernel(const float* __restrict__ fW1, const float* __restrict__ fb1,
            const float* __restrict__ fW2, const float* __restrict__ fb2,
            float* __restrict__ out) {
    int g = blockIdx.x;
    int t = threadIdx.x;
    __shared__ float sp[HD];
    __shared__ float red[HD];
    float inv = 1.0f / fmaxf(g_cnt[g], 1.0f);
    sp[t] = g_sums[(size_t)g * HD + t] * inv;
    __syncthreads();
    float acc = 0.f;
#pragma unroll 8
    for (int k = 0; k < HD; k++) acc = fmaf(sp[k], __ldg(&fW1[(size_t)k * HD + t]), acc);
    float hh = acc + __ldg(&fb1[t]);
    hh = (hh > 0.f) ? hh : hh * SLOPE;
    red[t] = hh * __ldg(&fW2[t]);
    __syncthreads();
    for (int s = 64; s > 0; s >>= 1) {
        if (t < s) red[t] += red[t + s];
        __syncthreads();
    }
    if (t == 0) out[g] = red[0] + __ldg(&fb2[0]);
}

// ============================================================
// launch
// ============================================================
extern "C" void kernel_launch(void* const* d_in, const int* in_sizes, int n_in,
                              void* d_out, int out_size) {
    const float* x     = (const float*)d_in[0];
    const void*  ei    = d_in[1];
    const void*  batch = d_in[2];
    const float* l0_W1   = (const float*)d_in[3];
    const float* l0_b1   = (const float*)d_in[4];
    const float* l0_W2   = (const float*)d_in[5];
    const float* l0_b2   = (const float*)d_in[6];
    const float* l0_Wres = (const float*)d_in[7];
    const float* Ws1 = (const float*)d_in[8];
    const float* bs1 = (const float*)d_in[9];
    const float* Ws2 = (const float*)d_in[10];
    const float* bs2 = (const float*)d_in[11];
    const float* fW1 = (const float*)d_in[12];
    const float* fb1 = (const float*)d_in[13];
    const float* fW2 = (const float*)d_in[14];
    const float* fb2 = (const float*)d_in[15];
    float* out = (float*)d_out;

    __half *agg, *h0, *h1;
    int *eiI, *batchI;
    cudaGetSymbolAddress((void**)&agg, g_agg);
    cudaGetSymbolAddress((void**)&h0, g_h0);
    cudaGetSymbolAddress((void**)&h1, g_h1);
    cudaGetSymbolAddress((void**)&eiI, g_ei);
    cudaGetSymbolAddress((void**)&batchI, g_batch);

    const int DSM_L0 = 137216 + 128 * LDF * 4;   // 204800
    const int DSM    = 137216;
    static bool attr_set = false;
    if (!attr_set) {
        cudaFuncSetAttribute(gin_wmma<64, true, false>,   cudaFuncAttributeMaxDynamicSharedMemorySize, DSM_L0);
        cudaFuncSetAttribute(gin_wmma<128, false, false>, cudaFuncAttributeMaxDynamicSharedMemorySize, DSM);
        cudaFuncSetAttribute(gin_wmma<128, false, true>,  cudaFuncAttributeMaxDynamicSharedMemorySize, DSM);
        attr_set = true;
    }

    // ---- index conversion + CSR build ----
    detect_dtype<<<1, 256>>>((const int*)ei);
    convert_idx<<<(2 * NE + 255) / 256, 256>>>(ei, eiI, 2 * NE);
    convert_idx<<<(NN + 255) / 256, 256>>>(batch, batchI, NN);
    zero_deg<<<(NN + 255) / 256, 256>>>();
    hist_dst<<<(NE + 255) / 256, 256>>>();
    scan_deg<<<1, 1024>>>();
    fill_csr<<<(NE + 255) / 256, 256>>>();

    const int blocks = (NN + 127) / 128;             // 391
    const int gblk = (NN * 16 + 255) / 256;          // half-warp per node

    // ---- layer 0 (64 -> 128, on-chip residual projection) ----
    gather_f32<<<gblk, 256>>>(x);
    gin_wmma<64, true, false><<<blocks, 256, DSM_L0>>>(
        agg, l0_W1, l0_b1, l0_W2, l0_b2, l0_Wres, x, nullptr, h0);

    zero_pool<<<(NG * HD + 255) / 256, 256>>>();
    pool_cnt<<<(NN + 255) / 256, 256>>>();

    // ---- layers 1..3 ----
    gather_f16<<<gblk, 256>>>(h0);
    gin_wmma<128, false, false><<<blocks, 256, DSM>>>(
        agg, Ws1, bs1, Ws2, bs2, nullptr, nullptr, h0, h1);

    gather_f16<<<gblk, 256>>>(h1);
    gin_wmma<128, false, false><<<blocks, 256, DSM>>>(
        agg, Ws1 + (size_t)HD * HD, bs1 + HD, Ws2 + (size_t)HD * HD, bs2 + HD, nullptr, nullptr, h1, h0);

    gather_f16<<<gblk, 256>>>(h0);
    gin_wmma<128, false, true><<<blocks, 256, DSM>>>(
        agg, Ws1 + (size_t)2 * HD * HD, bs1 + 2 * HD, Ws2 + (size_t)2 * HD * HD, bs2 + 2 * HD, nullptr, nullptr, h0, nullptr);

    // ---- head ----
    head_kernel<<<NG, 128>>>(fW1, fb1, fW2, fb2, out);
}

// round 9
// speedup vs baseline: 2.4971x; 1.2024x over previous
#include <cuda_runtime.h>
#include <cuda_fp16.h>
#include <mma.h>
#include <cstdint>

using namespace nvcuda;

// ---------------- problem constants ----------------
constexpr int NN = 50000;
constexpr int NE = 800000;
constexpr int IND = 64;
constexpr int HD = 128;
constexpr int NG = 1024;
constexpr float SLOPE = 0.01f;

constexpr int LDH = 136;   // half smem leading dim
constexpr int LDF = 132;   // float smem leading dim

// ---------------- scratch (device globals) ----------------
__device__ __align__(256) __half g_h0[(size_t)NN * HD];
__device__ __align__(256) __half g_h1[(size_t)NN * HD];
__device__ __align__(256) float g_sums[(size_t)NG * HD];
__device__ __align__(256) float g_cnt[NG];
__device__ __align__(256) int   g_ei[2 * NE];
__device__ __align__(256) int   g_batch[NN];
__device__ __align__(256) int   g_deg[NN];
__device__ __align__(256) int   g_cur[NN];
__device__ __align__(256) int   g_rowstart[NN + 1];
__device__ __align__(256) int   g_csr[NE];
__device__ int g_is64;

// ============================================================
// setup kernels
// ============================================================
__global__ void detect_dtype(const int* __restrict__ raw) {
    __shared__ int s_any;
    if (threadIdx.x == 0) s_any = 0;
    __syncthreads();
    int bad = 0;
    for (int i = threadIdx.x; i < 4096; i += blockDim.x) bad |= raw[2 * i + 1];
    if (bad) atomicOr(&s_any, 1);
    __syncthreads();
    if (threadIdx.x == 0) g_is64 = (s_any == 0) ? 1 : 0;
}
// zero deg + sums + cnt + cur (grid covers NG*HD = 131072)
__global__ void zero_misc() {
    int i = blockIdx.x * blockDim.x + threadIdx.x;
    if (i < NN) { g_deg[i] = 0; g_cur[i] = 0; }
    if (i < NG * HD) g_sums[i] = 0.f;
    if (i < NG) g_cnt[i] = 0.f;
}
// convert edge indices + histogram dst degrees
__global__ void conv_edges(const void* __restrict__ raw) {
    int i = blockIdx.x * blockDim.x + threadIdx.x;
    if (i >= 2 * NE) return;
    int v = g_is64 ? (int)((const long long*)raw)[i] : ((const int*)raw)[i];
    g_ei[i] = v;
    if (i >= NE) atomicAdd(&g_deg[v], 1);
}
// convert batch indices + per-graph node counts
__global__ void conv_batch(const void* __restrict__ raw) {
    int i = blockIdx.x * blockDim.x + threadIdx.x;
    if (i >= NN) return;
    int b = g_is64 ? (int)((const long long*)raw)[i] : ((const int*)raw)[i];
    g_batch[i] = b;
    atomicAdd(&g_cnt[b], 1.0f);
}
__global__ void __launch_bounds__(1024) scan_deg() {
    __shared__ int part[1024];
    int tid = threadIdx.x;
    const int CH = (NN + 1023) / 1024;
    int base = tid * CH;
    int s = 0;
    for (int i = 0; i < CH; i++) {
        int idx = base + i;
        if (idx < NN) s += g_deg[idx];
    }
    part[tid] = s;
    __syncthreads();
    for (int off = 1; off < 1024; off <<= 1) {
        int v = (tid >= off) ? part[tid - off] : 0;
        __syncthreads();
        part[tid] += v;
        __syncthreads();
    }
    int run = (tid > 0) ? part[tid - 1] : 0;
    for (int i = 0; i < CH; i++) {
        int idx = base + i;
        if (idx < NN) {
            g_rowstart[idx] = run;
            run += g_deg[idx];
        }
    }
    if (tid == 1023) g_rowstart[NN] = run;
}
__global__ void fill_csr() {
    int e = blockIdx.x * blockDim.x + threadIdx.x;
    if (e >= NE) return;
    int s = g_ei[e];
    int d = g_ei[NE + e];
    int p = atomicAdd(&g_cur[d], 1);
    g_csr[g_rowstart[d] + p] = s;
}

// ============================================================
// fully fused GIN layer: CSR gather into smem + two-GEMM fp16 MLP
//   A[row] = X[node] + sum_{src in csr[node]} X[src]   (gathered to sAh)
//   Out = relu( relu(A@W1 + b1) @ W2 + b2 + Res )
// L0: X = x fp32 (64-dim); Res = x @ Wres on-chip. Else X fp16, Res = X.
// POOL: epilogue pools fp32 into g_sums instead of writing h.
// Block: 512 threads = 16 warps. Warp w<8: row-tile w, cols 0..63;
// warp w+8: row-tile w, cols 64..127. Gather: 32 half-warps x 4 rows.
// ============================================================
template<int K1, bool L0, bool POOL>
__global__ void __launch_bounds__(512)
gin_fused(const __half* __restrict__ Xh,   // layers 1..3 input (h)
          const float* __restrict__ Xf,    // L0 raw x
          const float* __restrict__ W1, const float* __restrict__ b1,
          const float* __restrict__ W2, const float* __restrict__ b2,
          const float* __restrict__ Wres,
          __half* __restrict__ Out) {
    extern __shared__ char smc[];
    __half* sAh = (__half*)smc;                      // 128 x LDH half (34816 B)
    __half* sWh = (__half*)(smc + 34816);            // 128 x LDH half
    float*  sD  = (float*)(smc + 69632);             // 128 x LDF float (67584 B)
    float*  sR  = (float*)(smc + 137216);            // 128 x LDF float (L0 only)

    int tid = threadIdx.x;
    int wid = tid >> 5;
    int r0 = blockIdx.x * 128;
    int wrow = wid & 7;            // row-tile
    int nbase = (wid >> 3) * 4;    // n-frag base: 0 or 4

    wmma::fragment<wmma::accumulator, 16, 16, 16, float> acc[4];

    // W tile: fp32 [K][128] -> half smem
    auto loadW = [&](const float* __restrict__ src, int K) {
        int n = K * 32;
        for (int idx = tid; idx < n; idx += 512) {
            int row = idx >> 5, c4 = idx & 31;
            float4 v = __ldg((const float4*)(src + (size_t)row * 128) + c4);
            __half2* o = (__half2*)(sWh + row * LDH + c4 * 4);
            o[0] = __floats2half2_rn(v.x, v.y);
            o[1] = __floats2half2_rn(v.z, v.w);
        }
    };
    auto mmaPhase = [&](int ksteps) {
#pragma unroll
        for (int n = 0; n < 4; n++) wmma::fill_fragment(acc[n], 0.f);
        for (int k = 0; k < ksteps; k++) {
            wmma::fragment<wmma::matrix_a, 16, 16, 16, __half, wmma::row_major> af;
            wmma::load_matrix_sync(af, sAh + wrow * 16 * LDH + k * 16, LDH);
#pragma unroll
            for (int n = 0; n < 4; n++) {
                wmma::fragment<wmma::matrix_b, 16, 16, 16, __half, wmma::row_major> bf;
                wmma::load_matrix_sync(bf, sWh + k * 16 * LDH + (nbase + n) * 16, LDH);
                wmma::mma_sync(acc[n], af, bf, acc[n]);
            }
        }
    };
    auto storeAcc = [&](float* dst) {
#pragma unroll
        for (int n = 0; n < 4; n++)
            wmma::store_matrix_sync(dst + wrow * 16 * LDF + (nbase + n) * 16, acc[n], LDF, wmma::mem_row_major);
    };

    // ---- L0: stage raw x, project Res = x @ Wres -> sR ----
    if (L0) {
        for (int idx = tid; idx < 128 * 16; idx += 512) {
            int row = idx >> 4, c4 = idx & 15;
            float4 v = make_float4(0.f, 0.f, 0.f, 0.f);
            if (r0 + row < NN) v = __ldg((const float4*)(Xf + (size_t)(r0 + row) * 64) + c4);
            __half2* o = (__half2*)(sAh + row * LDH + c4 * 4);
            o[0] = __floats2half2_rn(v.x, v.y);
            o[1] = __floats2half2_rn(v.z, v.w);
        }
        loadW(Wres, 64);
        __syncthreads();
        mmaPhase(4);
        storeAcc(sR);
        __syncthreads();
    }

    // ---- gather into sAh + load W1 ----
    {
        int hw = tid >> 4;        // half-warp 0..31
        int t = tid & 15;
#pragma unroll
        for (int rr = 0; rr < 4; rr++) {
            int row = hw * 4 + rr;
            int node = r0 + row;
            if (L0) {
                // fp32 source, 64 cols: float4 chunk per thread
                float4 a = make_float4(0.f, 0.f, 0.f, 0.f);
                if (node < NN) {
                    a = __ldg((const float4*)(Xf + (size_t)node * 64) + t);
                    int beg = __ldg(&g_rowstart[node]);
                    int end = __ldg(&g_rowstart[node + 1]);
                    int i = beg;
                    for (; i + 2 <= end; i += 2) {
                        int s0 = __ldg(&g_csr[i + 0]);
                        int s1 = __ldg(&g_csr[i + 1]);
                        float4 v0 = __ldg((const float4*)(Xf + (size_t)s0 * 64) + t);
                        float4 v1 = __ldg((const float4*)(Xf + (size_t)s1 * 64) + t);
                        a.x += v0.x + v1.x; a.y += v0.y + v1.y;
                        a.z += v0.z + v1.z; a.w += v0.w + v1.w;
                    }
                    if (i < end) {
                        int s = __ldg(&g_csr[i]);
                        float4 v = __ldg((const float4*)(Xf + (size_t)s * 64) + t);
                        a.x += v.x; a.y += v.y; a.z += v.z; a.w += v.w;
                    }
                }
                __half2* o = (__half2*)(sAh + row * LDH + t * 4);
                o[0] = __floats2half2_rn(a.x, a.y);
                o[1] = __floats2half2_rn(a.z, a.w);
            } else {
                // fp16 source, 128 cols: uint4 chunk (8 halves) per thread
                const uint4* Xr = (const uint4*)Xh;
                float2 a[4] = {{0.f,0.f},{0.f,0.f},{0.f,0.f},{0.f,0.f}};
                if (node < NN) {
                    uint4 v = __ldg(Xr + (size_t)node * 16 + t);
                    const __half2* hh = (const __half2*)&v;
#pragma unroll
                    for (int q = 0; q < 4; q++) a[q] = __half22float2(hh[q]);
                    int beg = __ldg(&g_rowstart[node]);
                    int end = __ldg(&g_rowstart[node + 1]);
                    int i = beg;
                    for (; i + 2 <= end; i += 2) {
                        int s0 = __ldg(&g_csr[i + 0]);
                        int s1 = __ldg(&g_csr[i + 1]);
                        uint4 v0 = __ldg(Xr + (size_t)s0 * 16 + t);
                        uint4 v1 = __ldg(Xr + (size_t)s1 * 16 + t);
                        const __half2* h0 = (const __half2*)&v0;
                        const __half2* h1 = (const __half2*)&v1;
#pragma unroll
                        for (int q = 0; q < 4; q++) {
                            float2 f0 = __half22float2(h0[q]);
                            float2 f1 = __half22float2(h1[q]);
                            a[q].x += f0.x + f1.x;
                            a[q].y += f0.y + f1.y;
                        }
                    }
                    if (i < end) {
                        int s = __ldg(&g_csr[i]);
                        uint4 v2 = __ldg(Xr + (size_t)s * 16 + t);
                        const __half2* h2 = (const __half2*)&v2;
#pragma unroll
                        for (int q = 0; q < 4; q++) {
                            float2 f = __half22float2(h2[q]);
                            a[q].x += f.x;
                            a[q].y += f.y;
                        }
                    }
                }
                uint4 o;
                __half2* oh = (__half2*)&o;
#pragma unroll
                for (int q = 0; q < 4; q++) oh[q] = __floats2half2_rn(a[q].x, a[q].y);
                *(uint4*)(sAh + row * LDH + t * 8) = o;
            }
        }
    }
    loadW(W1, K1);
    __syncthreads();

    // ---- phase 1: T = relu(A @ W1 + b1) ----
    mmaPhase(K1 / 16);
    storeAcc(sD);
    __syncthreads();
    for (int idx = tid; idx < 128 * 128; idx += 512) {
        int row = idx >> 7, col = idx & 127;
        float v = fmaxf(sD[row * LDF + col] + __ldg(&b1[col]), 0.f);
        sAh[row * LDH + col] = __float2half_rn(v);
    }
    loadW(W2, 128);
    __syncthreads();

    // ---- phase 2: D = T @ W2 ----
    mmaPhase(8);
    __syncthreads();
    storeAcc(sD);
    __syncthreads();

    // ---- epilogue: o = relu(D + b2 + Res) ----
    for (int idx = tid; idx < 128 * 32; idx += 512) {
        int row = idx >> 5, c4 = idx & 31;
        int node = r0 + row;
        if (node >= NN) continue;
        float4 d = *(float4*)(sD + row * LDF + c4 * 4);
        float4 res4;
        if (L0) {
            res4 = *(float4*)(sR + row * LDF + c4 * 4);
        } else {
            uint2 rv = __ldg((const uint2*)(Xh + (size_t)node * HD + c4 * 4));
            const __half2* rh = (const __half2*)&rv;
            float2 r01 = __half22float2(rh[0]);
            float2 r23 = __half22float2(rh[1]);
            res4 = make_float4(r01.x, r01.y, r23.x, r23.y);
        }
        int col = c4 * 4;
        float4 o;
        o.x = fmaxf(d.x + __ldg(&b2[col + 0]) + res4.x, 0.f);
        o.y = fmaxf(d.y + __ldg(&b2[col + 1]) + res4.y, 0.f);
        o.z = fmaxf(d.z + __ldg(&b2[col + 2]) + res4.z, 0.f);
        o.w = fmaxf(d.w + __ldg(&b2[col + 3]) + res4.w, 0.f);
        if (POOL) {
            int b = __ldg(&g_batch[node]);
            float* p = g_sums + (size_t)b * HD + col;
            asm volatile("red.global.add.v4.f32 [%0], {%1,%2,%3,%4};"
                         :: "l"(p), "f"(o.x), "f"(o.y), "f"(o.z), "f"(o.w) : "memory");
        } else {
            uint2 ov;
            __half2* oh = (__half2*)&ov;
            oh[0] = __floats2half2_rn(o.x, o.y);
            oh[1] = __floats2half2_rn(o.z, o.w);
            *(uint2*)(Out + (size_t)node * HD + col) = ov;
        }
    }
}

// ============================================================
// fc head
// ============================================================
__global__ void __launch_bounds__(128)
head_kernel(const float* __restrict__ fW1, const float* __restrict__ fb1,
            const float* __restrict__ fW2, const float* __restrict__ fb2,
            float* __restrict__ out) {
    int g = blockIdx.x;
    int t = threadIdx.x;
    __shared__ float sp[HD];
    __shared__ float red[HD];
    float inv = 1.0f / fmaxf(g_cnt[g], 1.0f);
    sp[t] = g_sums[(size_t)g * HD + t] * inv;
    __syncthreads();
    float acc = 0.f;
#pragma unroll 8
    for (int k = 0; k < HD; k++) acc = fmaf(sp[k], __ldg(&fW1[(size_t)k * HD + t]), acc);
    float hh = acc + __ldg(&fb1[t]);
    hh = (hh > 0.f) ? hh : hh * SLOPE;
    red[t] = hh * __ldg(&fW2[t]);
    __syncthreads();
    for (int s = 64; s > 0; s >>= 1) {
        if (t < s) red[t] += red[t + s];
        __syncthreads();
    }
    if (t == 0) out[g] = red[0] + __ldg(&fb2[0]);
}

// ============================================================
// launch
// ============================================================
extern "C" void kernel_launch(void* const* d_in, const int* in_sizes, int n_in,
                              void* d_out, int out_size) {
    const float* x     = (const float*)d_in[0];
    const void*  ei    = d_in[1];
    const void*  batch = d_in[2];
    const float* l0_W1   = (const float*)d_in[3];
    const float* l0_b1   = (const float*)d_in[4];
    const float* l0_W2   = (const float*)d_in[5];
    const float* l0_b2   = (const float*)d_in[6];
    const float* l0_Wres = (const float*)d_in[7];
    const float* Ws1 = (const float*)d_in[8];
    const float* bs1 = (const float*)d_in[9];
    const float* Ws2 = (const float*)d_in[10];
    const float* bs2 = (const float*)d_in[11];
    const float* fW1 = (const float*)d_in[12];
    const float* fb1 = (const float*)d_in[13];
    const float* fW2 = (const float*)d_in[14];
    const float* fb2 = (const float*)d_in[15];
    float* out = (float*)d_out;

    __half *h0, *h1;
    cudaGetSymbolAddress((void**)&h0, g_h0);
    cudaGetSymbolAddress((void**)&h1, g_h1);

    const int DSM_L0 = 204800;
    const int DSM    = 137216;
    static bool attr_set = false;
    if (!attr_set) {
        cudaFuncSetAttribute(gin_fused<64, true, false>,   cudaFuncAttributeMaxDynamicSharedMemorySize, DSM_L0);
        cudaFuncSetAttribute(gin_fused<128, false, false>, cudaFuncAttributeMaxDynamicSharedMemorySize, DSM);
        cudaFuncSetAttribute(gin_fused<128, false, true>,  cudaFuncAttributeMaxDynamicSharedMemorySize, DSM);
        attr_set = true;
    }

    // ---- setup: dtype detect, zeroing, index conversion + CSR ----
    detect_dtype<<<1, 256>>>((const int*)ei);
    zero_misc<<<(NG * HD + 255) / 256, 256>>>();
    conv_edges<<<(2 * NE + 255) / 256, 256>>>(ei);
    conv_batch<<<(NN + 255) / 256, 256>>>(batch);
    scan_deg<<<1, 1024>>>();
    fill_csr<<<(NE + 255) / 256, 256>>>();

    const int blocks = (NN + 127) / 128;   // 391

    // ---- 4 fused GIN layers ----
    gin_fused<64, true, false><<<blocks, 512, DSM_L0>>>(
        nullptr, x, l0_W1, l0_b1, l0_W2, l0_b2, l0_Wres, h0);
    gin_fused<128, false, false><<<blocks, 512, DSM>>>(
        h0, nullptr, Ws1, bs1, Ws2, bs2, nullptr, h1);
    gin_fused<128, false, false><<<blocks, 512, DSM>>>(
        h1, nullptr, Ws1 + (size_t)HD * HD, bs1 + HD, Ws2 + (size_t)HD * HD, bs2 + HD, nullptr, h0);
    gin_fused<128, false, true><<<blocks, 512, DSM>>>(
        h0, nullptr, Ws1 + (size_t)2 * HD * HD, bs1 + 2 * HD, Ws2 + (size_t)2 * HD * HD, bs2 + 2 * HD, nullptr, nullptr);

    // ---- head ----
    head_kernel<<<NG, 128>>>(fW1, fb1, fW2, fb2, out);
}

// round 10
// speedup vs baseline: 2.5305x; 1.0134x over previous
#include <cuda_runtime.h>
#include <cuda_fp16.h>
#include <mma.h>
#include <cstdint>

using namespace nvcuda;

// ---------------- problem constants ----------------
constexpr int NN = 50000;
constexpr int NE = 800000;
constexpr int IND = 64;
constexpr int HD = 128;
constexpr int NG = 1024;
constexpr float SLOPE = 0.01f;

constexpr int LDH = 136;   // half smem leading dim
constexpr int LDF = 132;   // float smem leading dim

// ---------------- scratch (device globals) ----------------
__device__ __align__(256) __half g_h0[(size_t)NN * HD];
__device__ __align__(256) __half g_h1[(size_t)NN * HD];
__device__ __align__(256) __half g_wh[131072];       // all weights, fp16
__device__ __align__(256) float g_sums[(size_t)NG * HD];
__device__ __align__(256) int   g_batch[NN];
__device__ __align__(256) int   g_deg[NN];
__device__ __align__(256) int   g_cur[NN];
__device__ __align__(256) int   g_rowstart[NN + 1];
__device__ __align__(256) int   g_csr[NE];
__device__ int g_is64;

// weight offsets in g_wh (halves)
constexpr int OW_RES = 0;        // [64][128]
constexpr int OW_W10 = 8192;     // [64][128]
constexpr int OW_W20 = 16384;    // [128][128]
constexpr int OW_WS1 = 32768;    // 3 x [128][128]
constexpr int OW_WS2 = 81920;    // 3 x [128][128]

// ============================================================
// setup kernels
// ============================================================
// zero deg/cur/sums; block 0 additionally detects edge dtype
__global__ void zero_detect(const int* __restrict__ rawE) {
    int i = blockIdx.x * blockDim.x + threadIdx.x;
    if (i < NN) { g_deg[i] = 0; g_cur[i] = 0; }
    if (i < NG * HD) g_sums[i] = 0.f;
    if (blockIdx.x == 0) {
        __shared__ int s_any;
        if (threadIdx.x == 0) s_any = 0;
        __syncthreads();
        int bad = 0;
        for (int k = threadIdx.x; k < 4096; k += blockDim.x) bad |= rawE[2 * k + 1];
        if (bad) atomicOr(&s_any, 1);
        __syncthreads();
        if (threadIdx.x == 0) g_is64 = (s_any == 0) ? 1 : 0;
    }
}
// histogram dst degrees (reads raw) + convert batch indices
__global__ void hist_conv(const void* __restrict__ rawE, const void* __restrict__ rawB) {
    int i = blockIdx.x * blockDim.x + threadIdx.x;
    int is64 = g_is64;
    if (i < NE) {
        int d = is64 ? (int)((const long long*)rawE)[NE + i] : ((const int*)rawE)[NE + i];
        atomicAdd(&g_deg[d], 1);
    }
    if (i < NN) {
        g_batch[i] = is64 ? (int)((const long long*)rawB)[i] : ((const int*)rawB)[i];
    }
}
__global__ void __launch_bounds__(1024) scan_deg() {
    __shared__ int part[1024];
    int tid = threadIdx.x;
    const int CH = (NN + 1023) / 1024;
    int base = tid * CH;
    int s = 0;
    for (int i = 0; i < CH; i++) {
        int idx = base + i;
        if (idx < NN) s += g_deg[idx];
    }
    part[tid] = s;
    __syncthreads();
    for (int off = 1; off < 1024; off <<= 1) {
        int v = (tid >= off) ? part[tid - off] : 0;
        __syncthreads();
        part[tid] += v;
        __syncthreads();
    }
    int run = (tid > 0) ? part[tid - 1] : 0;
    for (int i = 0; i < CH; i++) {
        int idx = base + i;
        if (idx < NN) {
            g_rowstart[idx] = run;
            run += g_deg[idx];
        }
    }
    if (tid == 1023) g_rowstart[NN] = run;
}
// fill CSR reading raw edges directly
__global__ void fill_csr(const void* __restrict__ rawE) {
    int e = blockIdx.x * blockDim.x + threadIdx.x;
    if (e >= NE) return;
    int is64 = g_is64;
    int s = is64 ? (int)((const long long*)rawE)[e]      : ((const int*)rawE)[e];
    int d = is64 ? (int)((const long long*)rawE)[NE + e] : ((const int*)rawE)[NE + e];
    int p = atomicAdd(&g_cur[d], 1);
    g_csr[g_rowstart[d] + p] = s;
}
// convert all weights to fp16 (total 131072 elements)
__global__ void conv_weights(const float* __restrict__ l0_W1, const float* __restrict__ l0_W2,
                             const float* __restrict__ l0_Wres,
                             const float* __restrict__ Ws1, const float* __restrict__ Ws2) {
    int i = blockIdx.x * blockDim.x + threadIdx.x;
    if (i >= 131072) return;
    float v;
    if (i < 8192)        v = __ldg(&l0_Wres[i]);
    else if (i < 16384)  v = __ldg(&l0_W1[i - 8192]);
    else if (i < 32768)  v = __ldg(&l0_W2[i - 16384]);
    else if (i < 81920)  v = __ldg(&Ws1[i - 32768]);
    else                 v = __ldg(&Ws2[i - 81920]);
    g_wh[i] = __float2half_rn(v);
}

// ============================================================
// fully fused GIN layer: CSR gather into smem + two-GEMM fp16 MLP
//   A[row] = X[node] + sum_{src in csr[node]} X[src]
//   Out = relu( relu(A@W1 + b1) @ W2 + b2 + Res )
// Block: 512 threads = 16 warps. Warp w&7: row-tile; w>>3: n-half.
// ============================================================
template<int K1, bool L0, bool POOL>
__global__ void __launch_bounds__(512)
gin_fused(const __half* __restrict__ Xh,   // layers 1..3 input
          const float* __restrict__ Xf,    // L0 raw x
          const __half* __restrict__ W1, const float* __restrict__ b1,
          const __half* __restrict__ W2, const float* __restrict__ b2,
          const __half* __restrict__ Wres,
          __half* __restrict__ Out) {
    extern __shared__ char smc[];
    __half* sAh = (__half*)smc;                      // 128 x LDH half
    __half* sWh = (__half*)(smc + 34816);            // 128 x LDH half
    float*  sD  = (float*)(smc + 69632);             // 128 x LDF float
    float*  sR  = (float*)(smc + 137216);            // 128 x LDF float (L0)

    int tid = threadIdx.x;
    int wid = tid >> 5;
    int r0 = blockIdx.x * 128;
    int wrow = wid & 7;
    int nbase = (wid >> 3) * 4;

    wmma::fragment<wmma::accumulator, 16, 16, 16, float> acc[4];

    // W tile: fp16 [K][128] -> smem (plain vector copy)
    auto loadW = [&](const __half* __restrict__ src, int K) {
        int n = K * 16;
        for (int idx = tid; idx < n; idx += 512) {
            int row = idx >> 4, c = idx & 15;
            uint4 v = __ldg((const uint4*)src + (size_t)row * 16 + c);
            *(uint4*)(sWh + row * LDH + c * 8) = v;
        }
    };
    auto mmaPhase = [&](int ksteps) {
#pragma unroll
        for (int n = 0; n < 4; n++) wmma::fill_fragment(acc[n], 0.f);
        for (int k = 0; k < ksteps; k++) {
            wmma::fragment<wmma::matrix_a, 16, 16, 16, __half, wmma::row_major> af;
            wmma::load_matrix_sync(af, sAh + wrow * 16 * LDH + k * 16, LDH);
#pragma unroll
            for (int n = 0; n < 4; n++) {
                wmma::fragment<wmma::matrix_b, 16, 16, 16, __half, wmma::row_major> bf;
                wmma::load_matrix_sync(bf, sWh + k * 16 * LDH + (nbase + n) * 16, LDH);
                wmma::mma_sync(acc[n], af, bf, acc[n]);
            }
        }
    };
    auto storeAcc = [&](float* dst) {
#pragma unroll
        for (int n = 0; n < 4; n++)
            wmma::store_matrix_sync(dst + wrow * 16 * LDF + (nbase + n) * 16, acc[n], LDF, wmma::mem_row_major);
    };

    // ---- L0: stage raw x, project Res = x @ Wres -> sR ----
    if (L0) {
        for (int idx = tid; idx < 128 * 16; idx += 512) {
            int row = idx >> 4, c4 = idx & 15;
            float4 v = make_float4(0.f, 0.f, 0.f, 0.f);
            if (r0 + row < NN) v = __ldg((const float4*)(Xf + (size_t)(r0 + row) * 64) + c4);
            __half2* o = (__half2*)(sAh + row * LDH + c4 * 4);
            o[0] = __floats2half2_rn(v.x, v.y);
            o[1] = __floats2half2_rn(v.z, v.w);
        }
        loadW(Wres, 64);
        __syncthreads();
        mmaPhase(4);
        storeAcc(sR);
        __syncthreads();
    }

    // ---- gather into sAh (4-deep unrolled neighbor loads) ----
    {
        int hw = tid >> 4;
        int t = tid & 15;
#pragma unroll
        for (int rr = 0; rr < 4; rr++) {
            int row = hw * 4 + rr;
            int node = r0 + row;
            if (L0) {
                float4 a = make_float4(0.f, 0.f, 0.f, 0.f);
                if (node < NN) {
                    a = __ldg((const float4*)(Xf + (size_t)node * 64) + t);
                    int beg = __ldg(&g_rowstart[node]);
                    int end = __ldg(&g_rowstart[node + 1]);
                    int i = beg;
                    for (; i + 4 <= end; i += 4) {
                        int s0 = __ldg(&g_csr[i + 0]);
                        int s1 = __ldg(&g_csr[i + 1]);
                        int s2 = __ldg(&g_csr[i + 2]);
                        int s3 = __ldg(&g_csr[i + 3]);
                        float4 v0 = __ldg((const float4*)(Xf + (size_t)s0 * 64) + t);
                        float4 v1 = __ldg((const float4*)(Xf + (size_t)s1 * 64) + t);
                        float4 v2 = __ldg((const float4*)(Xf + (size_t)s2 * 64) + t);
                        float4 v3 = __ldg((const float4*)(Xf + (size_t)s3 * 64) + t);
                        a.x += (v0.x + v1.x) + (v2.x + v3.x);
                        a.y += (v0.y + v1.y) + (v2.y + v3.y);
                        a.z += (v0.z + v1.z) + (v2.z + v3.z);
                        a.w += (v0.w + v1.w) + (v2.w + v3.w);
                    }
                    for (; i < end; i++) {
                        int s = __ldg(&g_csr[i]);
                        float4 v = __ldg((const float4*)(Xf + (size_t)s * 64) + t);
                        a.x += v.x; a.y += v.y; a.z += v.z; a.w += v.w;
                    }
                }
                __half2* o = (__half2*)(sAh + row * LDH + t * 4);
                o[0] = __floats2half2_rn(a.x, a.y);
                o[1] = __floats2half2_rn(a.z, a.w);
            } else {
                const uint4* Xr = (const uint4*)Xh;
                float2 a[4] = {{0.f,0.f},{0.f,0.f},{0.f,0.f},{0.f,0.f}};
                if (node < NN) {
                    uint4 v = __ldg(Xr + (size_t)node * 16 + t);
                    const __half2* hh = (const __half2*)&v;
#pragma unroll
                    for (int q = 0; q < 4; q++) a[q] = __half22float2(hh[q]);
                    int beg = __ldg(&g_rowstart[node]);
                    int end = __ldg(&g_rowstart[node + 1]);
                    int i = beg;
                    for (; i + 4 <= end; i += 4) {
                        int s0 = __ldg(&g_csr[i + 0]);
                        int s1 = __ldg(&g_csr[i + 1]);
                        int s2 = __ldg(&g_csr[i + 2]);
                        int s3 = __ldg(&g_csr[i + 3]);
                        uint4 v0 = __ldg(Xr + (size_t)s0 * 16 + t);
                        uint4 v1 = __ldg(Xr + (size_t)s1 * 16 + t);
                        uint4 v2 = __ldg(Xr + (size_t)s2 * 16 + t);
                        uint4 v3 = __ldg(Xr + (size_t)s3 * 16 + t);
                        const __half2* h0 = (const __half2*)&v0;
                        const __half2* h1 = (const __half2*)&v1;
                        const __half2* h2 = (const __half2*)&v2;
                        const __half2* h3 = (const __half2*)&v3;
#pragma unroll
                        for (int q = 0; q < 4; q++) {
                            float2 f0 = __half22float2(h0[q]);
                            float2 f1 = __half22float2(h1[q]);
                            float2 f2 = __half22float2(h2[q]);
                            float2 f3 = __half22float2(h3[q]);
                            a[q].x += (f0.x + f1.x) + (f2.x + f3.x);
                            a[q].y += (f0.y + f1.y) + (f2.y + f3.y);
                        }
                    }
                    for (; i < end; i++) {
                        int s = __ldg(&g_csr[i]);
                        uint4 v2 = __ldg(Xr + (size_t)s * 16 + t);
                        const __half2* h2 = (const __half2*)&v2;
#pragma unroll
                        for (int q = 0; q < 4; q++) {
                            float2 f = __half22float2(h2[q]);
                            a[q].x += f.x;
                            a[q].y += f.y;
                        }
                    }
                }
                uint4 o;
                __half2* oh = (__half2*)&o;
#pragma unroll
                for (int q = 0; q < 4; q++) oh[q] = __floats2half2_rn(a[q].x, a[q].y);
                *(uint4*)(sAh + row * LDH + t * 8) = o;
            }
        }
    }
    loadW(W1, K1);
    __syncthreads();

    // ---- phase 1: T = relu(A @ W1 + b1) ----
    mmaPhase(K1 / 16);
    storeAcc(sD);
    __syncthreads();
    for (int idx = tid; idx < 128 * 128; idx += 512) {
        int row = idx >> 7, col = idx & 127;
        float v = fmaxf(sD[row * LDF + col] + __ldg(&b1[col]), 0.f);
        sAh[row * LDH + col] = __float2half_rn(v);
    }
    loadW(W2, 128);
    __syncthreads();

    // ---- phase 2: D = T @ W2 ----
    mmaPhase(8);
    __syncthreads();
    storeAcc(sD);
    __syncthreads();

    // ---- epilogue ----
    for (int idx = tid; idx < 128 * 32; idx += 512) {
        int row = idx >> 5, c4 = idx & 31;
        int node = r0 + row;
        if (node >= NN) continue;
        float4 d = *(float4*)(sD + row * LDF + c4 * 4);
        float4 res4;
        if (L0) {
            res4 = *(float4*)(sR + row * LDF + c4 * 4);
        } else {
            uint2 rv = __ldg((const uint2*)(Xh + (size_t)node * HD + c4 * 4));
            const __half2* rh = (const __half2*)&rv;
            float2 r01 = __half22float2(rh[0]);
            float2 r23 = __half22float2(rh[1]);
            res4 = make_float4(r01.x, r01.y, r23.x, r23.y);
        }
        int col = c4 * 4;
        float4 o;
        o.x = fmaxf(d.x + __ldg(&b2[col + 0]) + res4.x, 0.f);
        o.y = fmaxf(d.y + __ldg(&b2[col + 1]) + res4.y, 0.f);
        o.z = fmaxf(d.z + __ldg(&b2[col + 2]) + res4.z, 0.f);
        o.w = fmaxf(d.w + __ldg(&b2[col + 3]) + res4.w, 0.f);
        if (POOL) {
            int b = __ldg(&g_batch[node]);
            float* p = g_sums + (size_t)b * HD + col;
            asm volatile("red.global.add.v4.f32 [%0], {%1,%2,%3,%4};"
                         :: "l"(p), "f"(o.x), "f"(o.y), "f"(o.z), "f"(o.w) : "memory");
        } else {
            uint2 ov;
            __half2* oh = (__half2*)&ov;
            oh[0] = __floats2half2_rn(o.x, o.y);
            oh[1] = __floats2half2_rn(o.z, o.w);
            *(uint2*)(Out + (size_t)node * HD + col) = ov;
        }
    }
}

// ============================================================
// fc head (graph count via binary search on sorted batch)
// ============================================================
__global__ void __launch_bounds__(128)
head_kernel(const float* __restrict__ fW1, const float* __restrict__ fb1,
            const float* __restrict__ fW2, const float* __restrict__ fb2,
            float* __restrict__ out) {
    int g = blockIdx.x;
    int t = threadIdx.x;
    __shared__ float sp[HD];
    __shared__ float red[HD];
    __shared__ int s_cnt;
    if (t == 0) {
        int lo = 0, hi = NN;
        while (lo < hi) { int m = (lo + hi) >> 1; if (g_batch[m] < g) lo = m + 1; else hi = m; }
        int lo2 = lo, hi2 = NN;
        while (lo2 < hi2) { int m = (lo2 + hi2) >> 1; if (g_batch[m] < g + 1) lo2 = m + 1; else hi2 = m; }
        s_cnt = lo2 - lo;
    }
    __syncthreads();
    float inv = 1.0f / fmaxf((float)s_cnt, 1.0f);
    sp[t] = g_sums[(size_t)g * HD + t] * inv;
    __syncthreads();
    float acc = 0.f;
#pragma unroll 8
    for (int k = 0; k < HD; k++) acc = fmaf(sp[k], __ldg(&fW1[(size_t)k * HD + t]), acc);
    float hh = acc + __ldg(&fb1[t]);
    hh = (hh > 0.f) ? hh : hh * SLOPE;
    red[t] = hh * __ldg(&fW2[t]);
    __syncthreads();
    for (int s = 64; s > 0; s >>= 1) {
        if (t < s) red[t] += red[t + s];
        __syncthreads();
    }
    if (t == 0) out[g] = red[0] + __ldg(&fb2[0]);
}

// ============================================================
// launch
// ============================================================
extern "C" void kernel_launch(void* const* d_in, const int* in_sizes, int n_in,
                              void* d_out, int out_size) {
    const float* x     = (const float*)d_in[0];
    const void*  ei    = d_in[1];
    const void*  batch = d_in[2];
    const float* l0_W1   = (const float*)d_in[3];
    const float* l0_b1   = (const float*)d_in[4];
    const float* l0_W2   = (const float*)d_in[5];
    const float* l0_b2   = (const float*)d_in[6];
    const float* l0_Wres = (const float*)d_in[7];
    const float* Ws1 = (const float*)d_in[8];
    const float* bs1 = (const float*)d_in[9];
    const float* Ws2 = (const float*)d_in[10];
    const float* bs2 = (const float*)d_in[11];
    const float* fW1 = (const float*)d_in[12];
    const float* fb1 = (const float*)d_in[13];
    const float* fW2 = (const float*)d_in[14];
    const float* fb2 = (const float*)d_in[15];
    float* out = (float*)d_out;

    __half *h0, *h1, *wh;
    cudaGetSymbolAddress((void**)&h0, g_h0);
    cudaGetSymbolAddress((void**)&h1, g_h1);
    cudaGetSymbolAddress((void**)&wh, g_wh);

    const int DSM_L0 = 204800;
    const int DSM    = 137216;
    static bool attr_set = false;
    if (!attr_set) {
        cudaFuncSetAttribute(gin_fused<64, true, false>,   cudaFuncAttributeMaxDynamicSharedMemorySize, DSM_L0);
        cudaFuncSetAttribute(gin_fused<128, false, false>, cudaFuncAttributeMaxDynamicSharedMemorySize, DSM);
        cudaFuncSetAttribute(gin_fused<128, false, true>,  cudaFuncAttributeMaxDynamicSharedMemorySize, DSM);
        attr_set = true;
    }

    // ---- setup ----
    zero_detect<<<(NG * HD + 255) / 256, 256>>>((const int*)ei);
    hist_conv<<<(NE + 255) / 256, 256>>>(ei, batch);
    scan_deg<<<1, 1024>>>();
    fill_csr<<<(NE + 255) / 256, 256>>>(ei);
    conv_weights<<<(131072 + 255) / 256, 256>>>(l0_W1, l0_W2, l0_Wres, Ws1, Ws2);

    const int blocks = (NN + 127) / 128;   // 391

    // ---- 4 fused GIN layers ----
    gin_fused<64, true, false><<<blocks, 512, DSM_L0>>>(
        nullptr, x, wh + OW_W10, l0_b1, wh + OW_W20, l0_b2, wh + OW_RES, h0);
    gin_fused<128, false, false><<<blocks, 512, DSM>>>(
        h0, nullptr, wh + OW_WS1, bs1, wh + OW_WS2, bs2, nullptr, h1);
    gin_fused<128, false, false><<<blocks, 512, DSM>>>(
        h1, nullptr, wh + OW_WS1 + 16384, bs1 + HD, wh + OW_WS2 + 16384, bs2 + HD, nullptr, h0);
    gin_fused<128, false, true><<<blocks, 512, DSM>>>(
        h0, nullptr, wh + OW_WS1 + 32768, bs1 + 2 * HD, wh + OW_WS2 + 32768, bs2 + 2 * HD, nullptr, nullptr);

    // ---- head ----
    head_kernel<<<NG, 128>>>(fW1, fb1, fW2, fb2, out);
}

// round 11
// speedup vs baseline: 2.9983x; 1.1848x over previous
#include <cuda_runtime.h>
#include <cuda_fp16.h>
#include <mma.h>
#include <cstdint>

using namespace nvcuda;

// ---------------- problem constants ----------------
constexpr int NN = 50000;
constexpr int NE = 800000;
constexpr int IND = 64;
constexpr int HD = 128;
constexpr int NG = 1024;
constexpr float SLOPE = 0.01f;

constexpr int TM  = 64;    // rows per block tile
constexpr int LDH = 136;   // half smem leading dim
constexpr int LDF = 132;   // float smem leading dim

// ---------------- scratch (device globals) ----------------
__device__ __align__(256) __half g_h0[(size_t)NN * HD];
__device__ __align__(256) __half g_h1[(size_t)NN * HD];
__device__ __align__(256) __half g_wh[131072];       // all weights, fp16
__device__ __align__(256) float g_sums[(size_t)NG * HD];
__device__ __align__(256) int   g_batch[NN];
__device__ __align__(256) int   g_deg[NN];
__device__ __align__(256) int   g_cur[NN];
__device__ __align__(256) int   g_rowstart[NN + 1];
__device__ __align__(256) int   g_csr[NE];
__device__ int g_is64;

// weight offsets in g_wh (halves)
constexpr int OW_RES = 0;        // [64][128]
constexpr int OW_W10 = 8192;     // [64][128]
constexpr int OW_W20 = 16384;    // [128][128]
constexpr int OW_WS1 = 32768;    // 3 x [128][128]
constexpr int OW_WS2 = 81920;    // 3 x [128][128]

// ============================================================
// setup kernels
// ============================================================
__global__ void zero_detect(const int* __restrict__ rawE) {
    int i = blockIdx.x * blockDim.x + threadIdx.x;
    if (i < NN) { g_deg[i] = 0; g_cur[i] = 0; }
    if (i < NG * HD) g_sums[i] = 0.f;
    if (blockIdx.x == 0) {
        __shared__ int s_any;
        if (threadIdx.x == 0) s_any = 0;
        __syncthreads();
        int bad = 0;
        for (int k = threadIdx.x; k < 4096; k += blockDim.x) bad |= rawE[2 * k + 1];
        if (bad) atomicOr(&s_any, 1);
        __syncthreads();
        if (threadIdx.x == 0) g_is64 = (s_any == 0) ? 1 : 0;
    }
}
__global__ void hist_conv(const void* __restrict__ rawE, const void* __restrict__ rawB) {
    int i = blockIdx.x * blockDim.x + threadIdx.x;
    int is64 = g_is64;
    if (i < NE) {
        int d = is64 ? (int)((const long long*)rawE)[NE + i] : ((const int*)rawE)[NE + i];
        atomicAdd(&g_deg[d], 1);
    }
    if (i < NN) {
        g_batch[i] = is64 ? (int)((const long long*)rawB)[i] : ((const int*)rawB)[i];
    }
}
__global__ void __launch_bounds__(1024) scan_deg() {
    __shared__ int part[1024];
    int tid = threadIdx.x;
    const int CH = (NN + 1023) / 1024;
    int base = tid * CH;
    int s = 0;
    for (int i = 0; i < CH; i++) {
        int idx = base + i;
        if (idx < NN) s += g_deg[idx];
    }
    part[tid] = s;
    __syncthreads();
    for (int off = 1; off < 1024; off <<= 1) {
        int v = (tid >= off) ? part[tid - off] : 0;
        __syncthreads();
        part[tid] += v;
        __syncthreads();
    }
    int run = (tid > 0) ? part[tid - 1] : 0;
    for (int i = 0; i < CH; i++) {
        int idx = base + i;
        if (idx < NN) {
            g_rowstart[idx] = run;
            run += g_deg[idx];
        }
    }
    if (tid == 1023) g_rowstart[NN] = run;
}
__global__ void fill_csr(const void* __restrict__ rawE) {
    int e = blockIdx.x * blockDim.x + threadIdx.x;
    if (e >= NE) return;
    int is64 = g_is64;
    int s = is64 ? (int)((const long long*)rawE)[e]      : ((const int*)rawE)[e];
    int d = is64 ? (int)((const long long*)rawE)[NE + e] : ((const int*)rawE)[NE + e];
    int p = atomicAdd(&g_cur[d], 1);
    g_csr[g_rowstart[d] + p] = s;
}
__global__ void conv_weights(const float* __restrict__ l0_W1, const float* __restrict__ l0_W2,
                             const float* __restrict__ l0_Wres,
                             const float* __restrict__ Ws1, const float* __restrict__ Ws2) {
    int i = blockIdx.x * blockDim.x + threadIdx.x;
    if (i >= 131072) return;
    float v;
    if (i < 8192)        v = __ldg(&l0_Wres[i]);
    else if (i < 16384)  v = __ldg(&l0_W1[i - 8192]);
    else if (i < 32768)  v = __ldg(&l0_W2[i - 16384]);
    else if (i < 81920)  v = __ldg(&Ws1[i - 32768]);
    else                 v = __ldg(&Ws2[i - 81920]);
    g_wh[i] = __float2half_rn(v);
}

// ============================================================
// fused GIN layer, 64-row tile, 2 CTAs/SM:
//   A[row] = X[node] + sum_{src in csr[node]} X[src]
//   Out = relu( relu(A@W1 + b1) @ W2 + b2 + Res )
// L0: Res = x @ Wres accumulated directly into phase-2 registers.
// Block: 512 threads = 16 warps: wrow = wid&3 (4 row tiles),
// ngrp = wid>>2 (4 n-groups x 2 fragments of 16 cols).
// ============================================================
template<int K1, bool L0, bool POOL>
__global__ void __launch_bounds__(512, 2)
gin_fused(const __half* __restrict__ Xh,   // layers 1..3 input
          const float* __restrict__ Xf,    // L0 raw x
          const __half* __restrict__ W1, const float* __restrict__ b1,
          const __half* __restrict__ W2, const float* __restrict__ b2,
          const __half* __restrict__ Wres,
          __half* __restrict__ Out) {
    extern __shared__ char smc[];
    __half* sAh = (__half*)smc;                      // TM x LDH half   (17408 B)
    __half* sWh = (__half*)(smc + 17408);            // 128 x LDH half  (34816 B)
    float*  sD  = (float*)(smc + 52224);             // TM x LDF float  (33792 B)

    int tid = threadIdx.x;
    int wid = tid >> 5;
    int r0 = blockIdx.x * TM;
    int wrow = wid & 3;
    int nbase = (wid >> 2) * 2;

    wmma::fragment<wmma::accumulator, 16, 16, 16, float> acc[2];

    auto loadW = [&](const __half* __restrict__ src, int K) {
        int n = K * 16;
        for (int idx = tid; idx < n; idx += 512) {
            int row = idx >> 4, c = idx & 15;
            uint4 v = __ldg((const uint4*)src + (size_t)row * 16 + c);
            *(uint4*)(sWh + row * LDH + c * 8) = v;
        }
    };
    auto mmaAccum = [&](int ksteps) {   // accumulates onto existing acc
        for (int k = 0; k < ksteps; k++) {
            wmma::fragment<wmma::matrix_a, 16, 16, 16, __half, wmma::row_major> af;
            wmma::load_matrix_sync(af, sAh + wrow * 16 * LDH + k * 16, LDH);
#pragma unroll
            for (int n = 0; n < 2; n++) {
                wmma::fragment<wmma::matrix_b, 16, 16, 16, __half, wmma::row_major> bf;
                wmma::load_matrix_sync(bf, sWh + k * 16 * LDH + (nbase + n) * 16, LDH);
                wmma::mma_sync(acc[n], af, bf, acc[n]);
            }
        }
    };
    auto mmaPhase = [&](int ksteps) {
#pragma unroll
        for (int n = 0; n < 2; n++) wmma::fill_fragment(acc[n], 0.f);
        mmaAccum(ksteps);
    };
    auto storeAcc = [&]() {
#pragma unroll
        for (int n = 0; n < 2; n++)
            wmma::store_matrix_sync(sD + wrow * 16 * LDF + (nbase + n) * 16, acc[n], LDF, wmma::mem_row_major);
    };

    // ---- gather into sAh (2 rows per half-warp) ----
    {
        int hw = tid >> 4;
        int t = tid & 15;
#pragma unroll
        for (int rr = 0; rr < 2; rr++) {
            int row = hw * 2 + rr;
            int node = r0 + row;
            if (L0) {
                float4 a = make_float4(0.f, 0.f, 0.f, 0.f);
                if (node < NN) {
                    a = __ldg((const float4*)(Xf + (size_t)node * 64) + t);
                    int beg = __ldg(&g_rowstart[node]);
                    int end = __ldg(&g_rowstart[node + 1]);
                    int i = beg;
                    for (; i + 4 <= end; i += 4) {
                        int s0 = __ldg(&g_csr[i + 0]);
                        int s1 = __ldg(&g_csr[i + 1]);
                        int s2 = __ldg(&g_csr[i + 2]);
                        int s3 = __ldg(&g_csr[i + 3]);
                        float4 v0 = __ldg((const float4*)(Xf + (size_t)s0 * 64) + t);
                        float4 v1 = __ldg((const float4*)(Xf + (size_t)s1 * 64) + t);
                        float4 v2 = __ldg((const float4*)(Xf + (size_t)s2 * 64) + t);
                        float4 v3 = __ldg((const float4*)(Xf + (size_t)s3 * 64) + t);
                        a.x += (v0.x + v1.x) + (v2.x + v3.x);
                        a.y += (v0.y + v1.y) + (v2.y + v3.y);
                        a.z += (v0.z + v1.z) + (v2.z + v3.z);
                        a.w += (v0.w + v1.w) + (v2.w + v3.w);
                    }
                    for (; i < end; i++) {
                        int s = __ldg(&g_csr[i]);
                        float4 v = __ldg((const float4*)(Xf + (size_t)s * 64) + t);
                        a.x += v.x; a.y += v.y; a.z += v.z; a.w += v.w;
                    }
                }
                __half2* o = (__half2*)(sAh + row * LDH + t * 4);
                o[0] = __floats2half2_rn(a.x, a.y);
                o[1] = __floats2half2_rn(a.z, a.w);
            } else {
                const uint4* Xr = (const uint4*)Xh;
                float2 a[4] = {{0.f,0.f},{0.f,0.f},{0.f,0.f},{0.f,0.f}};
                if (node < NN) {
                    uint4 v = __ldg(Xr + (size_t)node * 16 + t);
                    const __half2* hh = (const __half2*)&v;
#pragma unroll
                    for (int q = 0; q < 4; q++) a[q] = __half22float2(hh[q]);
                    int beg = __ldg(&g_rowstart[node]);
                    int end = __ldg(&g_rowstart[node + 1]);
                    int i = beg;
                    for (; i + 4 <= end; i += 4) {
                        int s0 = __ldg(&g_csr[i + 0]);
                        int s1 = __ldg(&g_csr[i + 1]);
                        int s2 = __ldg(&g_csr[i + 2]);
                        int s3 = __ldg(&g_csr[i + 3]);
                        uint4 v0 = __ldg(Xr + (size_t)s0 * 16 + t);
                        uint4 v1 = __ldg(Xr + (size_t)s1 * 16 + t);
                        uint4 v2 = __ldg(Xr + (size_t)s2 * 16 + t);
                        uint4 v3 = __ldg(Xr + (size_t)s3 * 16 + t);
                        const __half2* h0 = (const __half2*)&v0;
                        const __half2* h1 = (const __half2*)&v1;
                        const __half2* h2 = (const __half2*)&v2;
                        const __half2* h3 = (const __half2*)&v3;
#pragma unroll
                        for (int q = 0; q < 4; q++) {
                            float2 f0 = __half22float2(h0[q]);
                            float2 f1 = __half22float2(h1[q]);
                            float2 f2 = __half22float2(h2[q]);
                            float2 f3 = __half22float2(h3[q]);
                            a[q].x += (f0.x + f1.x) + (f2.x + f3.x);
                            a[q].y += (f0.y + f1.y) + (f2.y + f3.y);
                        }
                    }
                    for (; i < end; i++) {
                        int s = __ldg(&g_csr[i]);
                        uint4 v2 = __ldg(Xr + (size_t)s * 16 + t);
                        const __half2* h2 = (const __half2*)&v2;
#pragma unroll
                        for (int q = 0; q < 4; q++) {
                            float2 f = __half22float2(h2[q]);
                            a[q].x += f.x;
                            a[q].y += f.y;
                        }
                    }
                }
                uint4 o;
                __half2* oh = (__half2*)&o;
#pragma unroll
                for (int q = 0; q < 4; q++) oh[q] = __floats2half2_rn(a[q].x, a[q].y);
                *(uint4*)(sAh + row * LDH + t * 8) = o;
            }
        }
    }
    loadW(W1, K1);
    __syncthreads();

    // ---- phase 1: T = relu(A @ W1 + b1) ----
    mmaPhase(K1 / 16);
    storeAcc();
    __syncthreads();
    for (int idx = tid; idx < TM * 128; idx += 512) {
        int row = idx >> 7, col = idx & 127;
        float v = fmaxf(sD[row * LDF + col] + __ldg(&b1[col]), 0.f);
        sAh[row * LDH + col] = __float2half_rn(v);
    }
    loadW(W2, 128);
    __syncthreads();

    // ---- phase 2: D = T @ W2 (keep acc in regs) ----
    mmaPhase(8);

    // ---- L0: acc += x @ Wres (register-resident residual) ----
    if (L0) {
        __syncthreads();   // all warps done reading sAh/sWh
        for (int idx = tid; idx < TM * 16; idx += 512) {
            int row = idx >> 4, c4 = idx & 15;
            float4 v = make_float4(0.f, 0.f, 0.f, 0.f);
            if (r0 + row < NN) v = __ldg((const float4*)(Xf + (size_t)(r0 + row) * 64) + c4);
            __half2* o = (__half2*)(sAh + row * LDH + c4 * 4);
            o[0] = __floats2half2_rn(v.x, v.y);
            o[1] = __floats2half2_rn(v.z, v.w);
        }
        loadW(Wres, 64);
        __syncthreads();
        mmaAccum(4);
    }
    __syncthreads();
    storeAcc();
    __syncthreads();

    // ---- epilogue: o = relu(D + b2 + Res) ----
    for (int idx = tid; idx < TM * 32; idx += 512) {
        int row = idx >> 5, c4 = idx & 31;
        int node = r0 + row;
        if (node >= NN) continue;
        float4 d = *(float4*)(sD + row * LDF + c4 * 4);
        float4 res4 = make_float4(0.f, 0.f, 0.f, 0.f);
        if (!L0) {
            uint2 rv = __ldg((const uint2*)(Xh + (size_t)node * HD + c4 * 4));
            const __half2* rh = (const __half2*)&rv;
            float2 r01 = __half22float2(rh[0]);
            float2 r23 = __half22float2(rh[1]);
            res4 = make_float4(r01.x, r01.y, r23.x, r23.y);
        }
        int col = c4 * 4;
        float4 o;
        o.x = fmaxf(d.x + __ldg(&b2[col + 0]) + res4.x, 0.f);
        o.y = fmaxf(d.y + __ldg(&b2[col + 1]) + res4.y, 0.f);
        o.z = fmaxf(d.z + __ldg(&b2[col + 2]) + res4.z, 0.f);
        o.w = fmaxf(d.w + __ldg(&b2[col + 3]) + res4.w, 0.f);
        if (POOL) {
            int b = __ldg(&g_batch[node]);
            float* p = g_sums + (size_t)b * HD + col;
            asm volatile("red.global.add.v4.f32 [%0], {%1,%2,%3,%4};"
                         :: "l"(p), "f"(o.x), "f"(o.y), "f"(o.z), "f"(o.w) : "memory");
        } else {
            uint2 ov;
            __half2* oh = (__half2*)&ov;
            oh[0] = __floats2half2_rn(o.x, o.y);
            oh[1] = __floats2half2_rn(o.z, o.w);
            *(uint2*)(Out + (size_t)node * HD + col) = ov;
        }
    }
}

// ============================================================
// fc head (graph count via binary search on sorted batch)
// ============================================================
__global__ void __launch_bounds__(128)
head_kernel(const float* __restrict__ fW1, const float* __restrict__ fb1,
            const float* __restrict__ fW2, const float* __restrict__ fb2,
            float* __restrict__ out) {
    int g = blockIdx.x;
    int t = threadIdx.x;
    __shared__ float sp[HD];
    __shared__ float red[HD];
    __shared__ int s_cnt;
    if (t == 0) {
        int lo = 0, hi = NN;
        while (lo < hi) { int m = (lo + hi) >> 1; if (g_batch[m] < g) lo = m + 1; else hi = m; }
        int lo2 = lo, hi2 = NN;
        while (lo2 < hi2) { int m = (lo2 + hi2) >> 1; if (g_batch[m] < g + 1) lo2 = m + 1; else hi2 = m; }
        s_cnt = lo2 - lo;
    }
    __syncthreads();
    float inv = 1.0f / fmaxf((float)s_cnt, 1.0f);
    sp[t] = g_sums[(size_t)g * HD + t] * inv;
    __syncthreads();
    float acc = 0.f;
#pragma unroll 8
    for (int k = 0; k < HD; k++) acc = fmaf(sp[k], __ldg(&fW1[(size_t)k * HD + t]), acc);
    float hh = acc + __ldg(&fb1[t]);
    hh = (hh > 0.f) ? hh : hh * SLOPE;
    red[t] = hh * __ldg(&fW2[t]);
    __syncthreads();
    for (int s = 64; s > 0; s >>= 1) {
        if (t < s) red[t] += red[t + s];
        __syncthreads();
    }
    if (t == 0) out[g] = red[0] + __ldg(&fb2[0]);
}

// ============================================================
// launch
// ============================================================
extern "C" void kernel_launch(void* const* d_in, const int* in_sizes, int n_in,
                              void* d_out, int out_size) {
    const float* x     = (const float*)d_in[0];
    const void*  ei    = d_in[1];
    const void*  batch = d_in[2];
    const float* l0_W1   = (const float*)d_in[3];
    const float* l0_b1   = (const float*)d_in[4];
    const float* l0_W2   = (const float*)d_in[5];
    const float* l0_b2   = (const float*)d_in[6];
    const float* l0_Wres = (const float*)d_in[7];
    const float* Ws1 = (const float*)d_in[8];
    const float* bs1 = (const float*)d_in[9];
    const float* Ws2 = (const float*)d_in[10];
    const float* bs2 = (const float*)d_in[11];
    const float* fW1 = (const float*)d_in[12];
    const float* fb1 = (const float*)d_in[13];
    const float* fW2 = (const float*)d_in[14];
    const float* fb2 = (const float*)d_in[15];
    float* out = (float*)d_out;

    __half *h0, *h1, *wh;
    cudaGetSymbolAddress((void**)&h0, g_h0);
    cudaGetSymbolAddress((void**)&h1, g_h1);
    cudaGetSymbolAddress((void**)&wh, g_wh);

    const int DSM = 86016;   // 17408 + 34816 + 33792
    static bool attr_set = false;
    if (!attr_set) {
        cudaFuncSetAttribute(gin_fused<64, true, false>,   cudaFuncAttributeMaxDynamicSharedMemorySize, DSM);
        cudaFuncSetAttribute(gin_fused<128, false, false>, cudaFuncAttributeMaxDynamicSharedMemorySize, DSM);
        cudaFuncSetAttribute(gin_fused<128, false, true>,  cudaFuncAttributeMaxDynamicSharedMemorySize, DSM);
        attr_set = true;
    }

    // ---- setup ----
    zero_detect<<<(NG * HD + 255) / 256, 256>>>((const int*)ei);
    hist_conv<<<(NE + 255) / 256, 256>>>(ei, batch);
    scan_deg<<<1, 1024>>>();
    fill_csr<<<(NE + 255) / 256, 256>>>(ei);
    conv_weights<<<(131072 + 255) / 256, 256>>>(l0_W1, l0_W2, l0_Wres, Ws1, Ws2);

    const int blocks = (NN + TM - 1) / TM;   // 782

    // ---- 4 fused GIN layers ----
    gin_fused<64, true, false><<<blocks, 512, DSM>>>(
        nullptr, x, wh + OW_W10, l0_b1, wh + OW_W20, l0_b2, wh + OW_RES, h0);
    gin_fused<128, false, false><<<blocks, 512, DSM>>>(
        h0, nullptr, wh + OW_WS1, bs1, wh + OW_WS2, bs2, nullptr, h1);
    gin_fused<128, false, false><<<blocks, 512, DSM>>>(
        h1, nullptr, wh + OW_WS1 + 16384, bs1 + HD, wh + OW_WS2 + 16384, bs2 + HD, nullptr, h0);
    gin_fused<128, false, true><<<blocks, 512, DSM>>>(
        h0, nullptr, wh + OW_WS1 + 32768, bs1 + 2 * HD, wh + OW_WS2 + 32768, bs2 + 2 * HD, nullptr, nullptr);

    // ---- head ----
    head_kernel<<<NG, 128>>>(fW1, fb1, fW2, fb2, out);
}

// round 12
// speedup vs baseline: 3.2384x; 1.0801x over previous
#include <cuda_runtime.h>
#include <cuda_fp16.h>
#include <mma.h>
#include <cstdint>

using namespace nvcuda;

// ---------------- problem constants ----------------
constexpr int NN = 50000;
constexpr int NE = 800000;
constexpr int IND = 64;
constexpr int HD = 128;
constexpr int NG = 1024;
constexpr float SLOPE = 0.01f;

constexpr int TM  = 64;    // rows per block tile
constexpr int LDH = 136;   // half smem leading dim
constexpr int LDF = 132;   // float smem leading dim

// ---------------- scratch (device globals) ----------------
__device__ __align__(256) __half g_h0[(size_t)NN * HD];
__device__ __align__(256) __half g_h1[(size_t)NN * HD];
__device__ __align__(256) __half g_wh[131072];       // all weights, fp16
__device__ __align__(256) float g_sums[(size_t)NG * HD];
__device__ __align__(256) int   g_batch[NN];
__device__ __align__(256) int   g_deg[NN];
__device__ __align__(256) int   g_cur[NN];
__device__ __align__(256) int   g_rowstart[NN + 1];
__device__ __align__(256) int   g_csr[NE];
__device__ int g_is64;

// weight offsets in g_wh (halves)
constexpr int OW_RES = 0;        // [64][128]
constexpr int OW_W10 = 8192;     // [64][128]
constexpr int OW_W20 = 16384;    // [128][128]
constexpr int OW_WS1 = 32768;    // 3 x [128][128]
constexpr int OW_WS2 = 81920;    // 3 x [128][128]

// ============================================================
// setup kernels
// ============================================================
__global__ void zero_detect(const int* __restrict__ rawE) {
    int i = blockIdx.x * blockDim.x + threadIdx.x;
    if (i < NN) { g_deg[i] = 0; g_cur[i] = 0; }
    if (i < NG * HD) g_sums[i] = 0.f;
    if (blockIdx.x == 0) {
        __shared__ int s_any;
        if (threadIdx.x == 0) s_any = 0;
        __syncthreads();
        int bad = 0;
        for (int k = threadIdx.x; k < 4096; k += blockDim.x) bad |= rawE[2 * k + 1];
        if (bad) atomicOr(&s_any, 1);
        __syncthreads();
        if (threadIdx.x == 0) g_is64 = (s_any == 0) ? 1 : 0;
    }
}
__global__ void hist_conv(const void* __restrict__ rawE, const void* __restrict__ rawB) {
    int i = blockIdx.x * blockDim.x + threadIdx.x;
    int is64 = g_is64;
    if (i < NE) {
        int d = is64 ? (int)((const long long*)rawE)[NE + i] : ((const int*)rawE)[NE + i];
        atomicAdd(&g_deg[d], 1);
    }
    if (i < NN) {
        g_batch[i] = is64 ? (int)((const long long*)rawB)[i] : ((const int*)rawB)[i];
    }
}
__global__ void __launch_bounds__(1024) scan_deg() {
    __shared__ int part[1024];
    int tid = threadIdx.x;
    const int CH = (NN + 1023) / 1024;
    int base = tid * CH;
    int s = 0;
    for (int i = 0; i < CH; i++) {
        int idx = base + i;
        if (idx < NN) s += g_deg[idx];
    }
    part[tid] = s;
    __syncthreads();
    for (int off = 1; off < 1024; off <<= 1) {
        int v = (tid >= off) ? part[tid - off] : 0;
        __syncthreads();
        part[tid] += v;
        __syncthreads();
    }
    int run = (tid > 0) ? part[tid - 1] : 0;
    for (int i = 0; i < CH; i++) {
        int idx = base + i;
        if (idx < NN) {
            g_rowstart[idx] = run;
            run += g_deg[idx];
        }
    }
    if (tid == 1023) g_rowstart[NN] = run;
}
__global__ void fill_csr(const void* __restrict__ rawE) {
    int e = blockIdx.x * blockDim.x + threadIdx.x;
    if (e >= NE) return;
    int is64 = g_is64;
    int s = is64 ? (int)((const long long*)rawE)[e]      : ((const int*)rawE)[e];
    int d = is64 ? (int)((const long long*)rawE)[NE + e] : ((const int*)rawE)[NE + e];
    int p = atomicAdd(&g_cur[d], 1);
    g_csr[g_rowstart[d] + p] = s;
}
__global__ void conv_weights(const float* __restrict__ l0_W1, const float* __restrict__ l0_W2,
                             const float* __restrict__ l0_Wres,
                             const float* __restrict__ Ws1, const float* __restrict__ Ws2) {
    int i = blockIdx.x * blockDim.x + threadIdx.x;
    if (i >= 131072) return;
    float v;
    if (i < 8192)        v = __ldg(&l0_Wres[i]);
    else if (i < 16384)  v = __ldg(&l0_W1[i - 8192]);
    else if (i < 32768)  v = __ldg(&l0_W2[i - 16384]);
    else if (i < 81920)  v = __ldg(&Ws1[i - 32768]);
    else                 v = __ldg(&Ws2[i - 81920]);
    g_wh[i] = __float2half_rn(v);
}

// ============================================================
// fused GIN layer, 64-row tile, smem-aliased D staging, 3 CTAs/SM:
//   A[row] = X[node] + sum_{src in csr[node]} X[src]
//   Out = relu( relu(A@W1 + b1) @ W2 + b2 + Res )
// sD ALIASES sWh: each MMA phase finishes reading weights before its
// accumulators are staged, so the region is reused (extra sync per phase).
// L0: Res = x @ Wres accumulated directly into phase-2 registers.
// ============================================================
template<int K1, bool L0, bool POOL>
__global__ void __launch_bounds__(512, 3)
gin_fused(const __half* __restrict__ Xh,   // layers 1..3 input
          const float* __restrict__ Xf,    // L0 raw x
          const __half* __restrict__ W1, const float* __restrict__ b1,
          const __half* __restrict__ W2, const float* __restrict__ b2,
          const __half* __restrict__ Wres,
          __half* __restrict__ Out) {
    extern __shared__ char smc[];
    __half* sAh = (__half*)smc;                      // TM x LDH half   (17408 B)
    __half* sWh = (__half*)(smc + 17408);            // 128 x LDH half  (34816 B)
    float*  sD  = (float*)(smc + 17408);             // ALIAS of sWh (TM x LDF = 33792 B)

    int tid = threadIdx.x;
    int wid = tid >> 5;
    int r0 = blockIdx.x * TM;
    int wrow = wid & 3;
    int nbase = (wid >> 2) * 2;

    wmma::fragment<wmma::accumulator, 16, 16, 16, float> acc[2];

    auto loadW = [&](const __half* __restrict__ src, int K) {
        int n = K * 16;
        for (int idx = tid; idx < n; idx += 512) {
            int row = idx >> 4, c = idx & 15;
            uint4 v = __ldg((const uint4*)src + (size_t)row * 16 + c);
            *(uint4*)(sWh + row * LDH + c * 8) = v;
        }
    };
    auto mmaAccum = [&](int ksteps) {
        for (int k = 0; k < ksteps; k++) {
            wmma::fragment<wmma::matrix_a, 16, 16, 16, __half, wmma::row_major> af;
            wmma::load_matrix_sync(af, sAh + wrow * 16 * LDH + k * 16, LDH);
#pragma unroll
            for (int n = 0; n < 2; n++) {
                wmma::fragment<wmma::matrix_b, 16, 16, 16, __half, wmma::row_major> bf;
                wmma::load_matrix_sync(bf, sWh + k * 16 * LDH + (nbase + n) * 16, LDH);
                wmma::mma_sync(acc[n], af, bf, acc[n]);
            }
        }
    };
    auto mmaPhase = [&](int ksteps) {
#pragma unroll
        for (int n = 0; n < 2; n++) wmma::fill_fragment(acc[n], 0.f);
        mmaAccum(ksteps);
    };
    auto storeAcc = [&]() {
#pragma unroll
        for (int n = 0; n < 2; n++)
            wmma::store_matrix_sync(sD + wrow * 16 * LDF + (nbase + n) * 16, acc[n], LDF, wmma::mem_row_major);
    };

    // ---- gather into sAh (2 rows per half-warp) ----
    {
        int hw = tid >> 4;
        int t = tid & 15;
#pragma unroll
        for (int rr = 0; rr < 2; rr++) {
            int row = hw * 2 + rr;
            int node = r0 + row;
            if (L0) {
                float4 a = make_float4(0.f, 0.f, 0.f, 0.f);
                if (node < NN) {
                    a = __ldg((const float4*)(Xf + (size_t)node * 64) + t);
                    int beg = __ldg(&g_rowstart[node]);
                    int end = __ldg(&g_rowstart[node + 1]);
                    int i = beg;
                    for (; i + 4 <= end; i += 4) {
                        int s0 = __ldg(&g_csr[i + 0]);
                        int s1 = __ldg(&g_csr[i + 1]);
                        int s2 = __ldg(&g_csr[i + 2]);
                        int s3 = __ldg(&g_csr[i + 3]);
                        float4 v0 = __ldg((const float4*)(Xf + (size_t)s0 * 64) + t);
                        float4 v1 = __ldg((const float4*)(Xf + (size_t)s1 * 64) + t);
                        float4 v2 = __ldg((const float4*)(Xf + (size_t)s2 * 64) + t);
                        float4 v3 = __ldg((const float4*)(Xf + (size_t)s3 * 64) + t);
                        a.x += (v0.x + v1.x) + (v2.x + v3.x);
                        a.y += (v0.y + v1.y) + (v2.y + v3.y);
                        a.z += (v0.z + v1.z) + (v2.z + v3.z);
                        a.w += (v0.w + v1.w) + (v2.w + v3.w);
                    }
                    for (; i < end; i++) {
                        int s = __ldg(&g_csr[i]);
                        float4 v = __ldg((const float4*)(Xf + (size_t)s * 64) + t);
                        a.x += v.x; a.y += v.y; a.z += v.z; a.w += v.w;
                    }
                }
                __half2* o = (__half2*)(sAh + row * LDH + t * 4);
                o[0] = __floats2half2_rn(a.x, a.y);
                o[1] = __floats2half2_rn(a.z, a.w);
            } else {
                const uint4* Xr = (const uint4*)Xh;
                float2 a[4] = {{0.f,0.f},{0.f,0.f},{0.f,0.f},{0.f,0.f}};
                if (node < NN) {
                    uint4 v = __ldg(Xr + (size_t)node * 16 + t);
                    const __half2* hh = (const __half2*)&v;
#pragma unroll
                    for (int q = 0; q < 4; q++) a[q] = __half22float2(hh[q]);
                    int beg = __ldg(&g_rowstart[node]);
                    int end = __ldg(&g_rowstart[node + 1]);
                    int i = beg;
                    for (; i + 4 <= end; i += 4) {
                        int s0 = __ldg(&g_csr[i + 0]);
                        int s1 = __ldg(&g_csr[i + 1]);
                        int s2 = __ldg(&g_csr[i + 2]);
                        int s3 = __ldg(&g_csr[i + 3]);
                        uint4 v0 = __ldg(Xr + (size_t)s0 * 16 + t);
                        uint4 v1 = __ldg(Xr + (size_t)s1 * 16 + t);
                        uint4 v2 = __ldg(Xr + (size_t)s2 * 16 + t);
                        uint4 v3 = __ldg(Xr + (size_t)s3 * 16 + t);
                        const __half2* h0 = (const __half2*)&v0;
                        const __half2* h1 = (const __half2*)&v1;
                        const __half2* h2 = (const __half2*)&v2;
                        const __half2* h3 = (const __half2*)&v3;
#pragma unroll
                        for (int q = 0; q < 4; q++) {
                            float2 f0 = __half22float2(h0[q]);
                            float2 f1 = __half22float2(h1[q]);
                            float2 f2 = __half22float2(h2[q]);
                            float2 f3 = __half22float2(h3[q]);
                            a[q].x += (f0.x + f1.x) + (f2.x + f3.x);
                            a[q].y += (f0.y + f1.y) + (f2.y + f3.y);
                        }
                    }
                    for (; i < end; i++) {
                        int s = __ldg(&g_csr[i]);
                        uint4 v2 = __ldg(Xr + (size_t)s * 16 + t);
                        const __half2* h2 = (const __half2*)&v2;
#pragma unroll
                        for (int q = 0; q < 4; q++) {
                            float2 f = __half22float2(h2[q]);
                            a[q].x += f.x;
                            a[q].y += f.y;
                        }
                    }
                }
                uint4 o;
                __half2* oh = (__half2*)&o;
#pragma unroll
                for (int q = 0; q < 4; q++) oh[q] = __floats2half2_rn(a[q].x, a[q].y);
                *(uint4*)(sAh + row * LDH + t * 8) = o;
            }
        }
    }
    loadW(W1, K1);
    __syncthreads();

    // ---- phase 1: T = relu(A @ W1 + b1) ----
    mmaPhase(K1 / 16);
    __syncthreads();            // all warps done reading sWh (W1)
    storeAcc();                 // write sD (aliases sWh)
    __syncthreads();
    for (int idx = tid; idx < TM * 128; idx += 512) {
        int row = idx >> 7, col = idx & 127;
        float v = fmaxf(sD[row * LDF + col] + __ldg(&b1[col]), 0.f);
        sAh[row * LDH + col] = __float2half_rn(v);
    }
    __syncthreads();            // relu reads of sD done
    loadW(W2, 128);             // overwrite the aliased region with W2
    __syncthreads();

    // ---- phase 2: D = T @ W2 (acc stays in regs) ----
    mmaPhase(8);

    // ---- L0: acc += x @ Wres (register-resident residual) ----
    if (L0) {
        __syncthreads();        // all warps done reading sAh / sWh
        for (int idx = tid; idx < TM * 16; idx += 512) {
            int row = idx >> 4, c4 = idx & 15;
            float4 v = make_float4(0.f, 0.f, 0.f, 0.f);
            if (r0 + row < NN) v = __ldg((const float4*)(Xf + (size_t)(r0 + row) * 64) + c4);
            __half2* o = (__half2*)(sAh + row * LDH + c4 * 4);
            o[0] = __floats2half2_rn(v.x, v.y);
            o[1] = __floats2half2_rn(v.z, v.w);
        }
        loadW(Wres, 64);
        __syncthreads();
        mmaAccum(4);
    }
    __syncthreads();            // all warps done reading sWh
    storeAcc();                 // write sD (aliases sWh)
    __syncthreads();

    // ---- epilogue: o = relu(D + b2 + Res) ----
    for (int idx = tid; idx < TM * 32; idx += 512) {
        int row = idx >> 5, c4 = idx & 31;
        int node = r0 + row;
        if (node >= NN) continue;
        float4 d = *(float4*)(sD + row * LDF + c4 * 4);
        float4 res4 = make_float4(0.f, 0.f, 0.f, 0.f);
        if (!L0) {
            uint2 rv = __ldg((const uint2*)(Xh + (size_t)node * HD + c4 * 4));
            const __half2* rh = (const __half2*)&rv;
            float2 r01 = __half22float2(rh[0]);
            float2 r23 = __half22float2(rh[1]);
            res4 = make_float4(r01.x, r01.y, r23.x, r23.y);
        }
        int col = c4 * 4;
        float4 o;
        o.x = fmaxf(d.x + __ldg(&b2[col + 0]) + res4.x, 0.f);
        o.y = fmaxf(d.y + __ldg(&b2[col + 1]) + res4.y, 0.f);
        o.z = fmaxf(d.z + __ldg(&b2[col + 2]) + res4.z, 0.f);
        o.w = fmaxf(d.w + __ldg(&b2[col + 3]) + res4.w, 0.f);
        if (POOL) {
            int b = __ldg(&g_batch[node]);
            float* p = g_sums + (size_t)b * HD + col;
            asm volatile("red.global.add.v4.f32 [%0], {%1,%2,%3,%4};"
                         :: "l"(p), "f"(o.x), "f"(o.y), "f"(o.z), "f"(o.w) : "memory");
        } else {
            uint2 ov;
            __half2* oh = (__half2*)&ov;
            oh[0] = __floats2half2_rn(o.x, o.y);
            oh[1] = __floats2half2_rn(o.z, o.w);
            *(uint2*)(Out + (size_t)node * HD + col) = ov;
        }
    }
}

// ============================================================
// fc head (graph count via binary search on sorted batch)
// ============================================================
__global__ void __launch_bounds__(128)
head_kernel(const float* __restrict__ fW1, const float* __restrict__ fb1,
            const float* __restrict__ fW2, const float* __restrict__ fb2,
            float* __restrict__ out) {
    int g = blockIdx.x;
    int t = threadIdx.x;
    __shared__ float sp[HD];
    __shared__ float red[HD];
    __shared__ int s_cnt;
    if (t == 0) {
        int lo = 0, hi = NN;
        while (lo < hi) { int m = (lo + hi) >> 1; if (g_batch[m] < g) lo = m + 1; else hi = m; }
        int lo2 = lo, hi2 = NN;
        while (lo2 < hi2) { int m = (lo2 + hi2) >> 1; if (g_batch[m] < g + 1) lo2 = m + 1; else hi2 = m; }
        s_cnt = lo2 - lo;
    }
    __syncthreads();
    float inv = 1.0f / fmaxf((float)s_cnt, 1.0f);
    sp[t] = g_sums[(size_t)g * HD + t] * inv;
    __syncthreads();
    float acc = 0.f;
#pragma unroll 8
    for (int k = 0; k < HD; k++) acc = fmaf(sp[k], __ldg(&fW1[(size_t)k * HD + t]), acc);
    float hh = acc + __ldg(&fb1[t]);
    hh = (hh > 0.f) ? hh : hh * SLOPE;
    red[t] = hh * __ldg(&fW2[t]);
    __syncthreads();
    for (int s = 64; s > 0; s >>= 1) {
        if (t < s) red[t] += red[t + s];
        __syncthreads();
    }
    if (t == 0) out[g] = red[0] + __ldg(&fb2[0]);
}

// ============================================================
// launch
// ============================================================
extern "C" void kernel_launch(void* const* d_in, const int* in_sizes, int n_in,
                              void* d_out, int out_size) {
    const float* x     = (const float*)d_in[0];
    const void*  ei    = d_in[1];
    const void*  batch = d_in[2];
    const float* l0_W1   = (const float*)d_in[3];
    const float* l0_b1   = (const float*)d_in[4];
    const float* l0_W2   = (const float*)d_in[5];
    const float* l0_b2   = (const float*)d_in[6];
    const float* l0_Wres = (const float*)d_in[7];
    const float* Ws1 = (const float*)d_in[8];
    const float* bs1 = (const float*)d_in[9];
    const float* Ws2 = (const float*)d_in[10];
    const float* bs2 = (const float*)d_in[11];
    const float* fW1 = (const float*)d_in[12];
    const float* fb1 = (const float*)d_in[13];
    const float* fW2 = (const float*)d_in[14];
    const float* fb2 = (const float*)d_in[15];
    float* out = (float*)d_out;

    __half *h0, *h1, *wh;
    cudaGetSymbolAddress((void**)&h0, g_h0);
    cudaGetSymbolAddress((void**)&h1, g_h1);
    cudaGetSymbolAddress((void**)&wh, g_wh);

    const int DSM = 52224;   // sAh(17408) + sWh(34816); sD aliases sWh
    static bool attr_set = false;
    if (!attr_set) {
        cudaFuncSetAttribute(gin_fused<64, true, false>,   cudaFuncAttributeMaxDynamicSharedMemorySize, DSM);
        cudaFuncSetAttribute(gin_fused<128, false, false>, cudaFuncAttributeMaxDynamicSharedMemorySize, DSM);
        cudaFuncSetAttribute(gin_fused<128, false, true>,  cudaFuncAttributeMaxDynamicSharedMemorySize, DSM);
        attr_set = true;
    }

    // ---- setup ----
    zero_detect<<<(NG * HD + 255) / 256, 256>>>((const int*)ei);
    hist_conv<<<(NE + 255) / 256, 256>>>(ei, batch);
    scan_deg<<<1, 1024>>>();
    fill_csr<<<(NE + 255) / 256, 256>>>(ei);
    conv_weights<<<(131072 + 255) / 256, 256>>>(l0_W1, l0_W2, l0_Wres, Ws1, Ws2);

    const int blocks = (NN + TM - 1) / TM;   // 782

    // ---- 4 fused GIN layers ----
    gin_fused<64, true, false><<<blocks, 512, DSM>>>(
        nullptr, x, wh + OW_W10, l0_b1, wh + OW_W20, l0_b2, wh + OW_RES, h0);
    gin_fused<128, false, false><<<blocks, 512, DSM>>>(
        h0, nullptr, wh + OW_WS1, bs1, wh + OW_WS2, bs2, nullptr, h1);
    gin_fused<128, false, false><<<blocks, 512, DSM>>>(
        h1, nullptr, wh + OW_WS1 + 16384, bs1 + HD, wh + OW_WS2 + 16384, bs2 + HD, nullptr, h0);
    gin_fused<128, false, true><<<blocks, 512, DSM>>>(
        h0, nullptr, wh + OW_WS1 + 32768, bs1 + 2 * HD, wh + OW_WS2 + 32768, bs2 + 2 * HD, nullptr, nullptr);

    // ---- head ----
    head_kernel<<<NG, 128>>>(fW1, fb1, fW2, fb2, out);
}

// round 13
// speedup vs baseline: 3.2388x; 1.0001x over previous
#include <cuda_runtime.h>
#include <cuda_fp16.h>
#include <mma.h>
#include <cstdint>

using namespace nvcuda;

// ---------------- problem constants ----------------
constexpr int NN = 50000;
constexpr int NE = 800000;
constexpr int IND = 64;
constexpr int HD = 128;
constexpr int NG = 1024;
constexpr float SLOPE = 0.01f;

constexpr int TM  = 64;    // rows per block tile
constexpr int LDH = 136;   // half smem leading dim
constexpr int LDF = 132;   // float smem leading dim

// ---------------- scratch (device globals) ----------------
__device__ __align__(256) __half g_h0[(size_t)NN * HD];
__device__ __align__(256) __half g_h1[(size_t)NN * HD];
__device__ __align__(256) __half g_wh[131072];       // all weights, fp16
__device__ __align__(256) float g_sums[(size_t)NG * HD];
__device__ __align__(256) int   g_batch[NN];
__device__ __align__(256) int   g_deg[NN];
__device__ __align__(256) int   g_cur[NN];
__device__ __align__(256) int   g_rowstart[NN + 1];
__device__ __align__(256) int   g_csr[NE];
__device__ int g_is64;

// weight offsets in g_wh (halves)
constexpr int OW_RES = 0;        // [64][128]
constexpr int OW_W10 = 8192;     // [64][128]
constexpr int OW_W20 = 16384;    // [128][128]
constexpr int OW_WS1 = 32768;    // 3 x [128][128]
constexpr int OW_WS2 = 81920;    // 3 x [128][128]

// ============================================================
// setup kernels
// ============================================================
__global__ void zero_detect(const int* __restrict__ rawE) {
    int i = blockIdx.x * blockDim.x + threadIdx.x;
    if (i < NN) { g_deg[i] = 0; g_cur[i] = 0; }
    if (i < NG * HD) g_sums[i] = 0.f;
    if (blockIdx.x == 0) {
        __shared__ int s_any;
        if (threadIdx.x == 0) s_any = 0;
        __syncthreads();
        int bad = 0;
        for (int k = threadIdx.x; k < 4096; k += blockDim.x) bad |= rawE[2 * k + 1];
        if (bad) atomicOr(&s_any, 1);
        __syncthreads();
        if (threadIdx.x == 0) g_is64 = (s_any == 0) ? 1 : 0;
    }
}
__global__ void hist_conv(const void* __restrict__ rawE, const void* __restrict__ rawB) {
    int i = blockIdx.x * blockDim.x + threadIdx.x;
    int is64 = g_is64;
    if (i < NE) {
        int d = is64 ? (int)((const long long*)rawE)[NE + i] : ((const int*)rawE)[NE + i];
        atomicAdd(&g_deg[d], 1);
    }
    if (i < NN) {
        g_batch[i] = is64 ? (int)((const long long*)rawB)[i] : ((const int*)rawB)[i];
    }
}
__global__ void __launch_bounds__(1024) scan_deg() {
    __shared__ int part[1024];
    int tid = threadIdx.x;
    const int CH = (NN + 1023) / 1024;
    int base = tid * CH;
    int s = 0;
    for (int i = 0; i < CH; i++) {
        int idx = base + i;
        if (idx < NN) s += g_deg[idx];
    }
    part[tid] = s;
    __syncthreads();
    for (int off = 1; off < 1024; off <<= 1) {
        int v = (tid >= off) ? part[tid - off] : 0;
        __syncthreads();
        part[tid] += v;
        __syncthreads();
    }
    int run = (tid > 0) ? part[tid - 1] : 0;
    for (int i = 0; i < CH; i++) {
        int idx = base + i;
        if (idx < NN) {
            g_rowstart[idx] = run;
            run += g_deg[idx];
        }
    }
    if (tid == 1023) g_rowstart[NN] = run;
}
// fill CSR + convert weights (independent work fused into one launch)
__global__ void fill_csr_convw(const void* __restrict__ rawE,
                               const float* __restrict__ l0_W1, const float* __restrict__ l0_W2,
                               const float* __restrict__ l0_Wres,
                               const float* __restrict__ Ws1, const float* __restrict__ Ws2) {
    int e = blockIdx.x * blockDim.x + threadIdx.x;
    if (e < 131072) {
        float v;
        if (e < 8192)        v = __ldg(&l0_Wres[e]);
        else if (e < 16384)  v = __ldg(&l0_W1[e - 8192]);
        else if (e < 32768)  v = __ldg(&l0_W2[e - 16384]);
        else if (e < 81920)  v = __ldg(&Ws1[e - 32768]);
        else                 v = __ldg(&Ws2[e - 81920]);
        g_wh[e] = __float2half_rn(v);
    }
    if (e >= NE) return;
    int is64 = g_is64;
    int s = is64 ? (int)((const long long*)rawE)[e]      : ((const int*)rawE)[e];
    int d = is64 ? (int)((const long long*)rawE)[NE + e] : ((const int*)rawE)[NE + e];
    int p = atomicAdd(&g_cur[d], 1);
    g_csr[g_rowstart[d] + p] = s;
}

// ============================================================
// fused GIN layer, 64-row tile, smem-aliased D staging, 3 CTAs/SM:
//   A[row] = X[node] + sum_{src in csr[node]} X[src]
//   Out = relu( relu(A@W1 + b1) @ W2 + b2 + Res )
// sD ALIASES sWh (extra sync sequences W-read before acc-store).
// CSR index prefetch double-buffers the next 4 neighbor ids so the
// idx->row dependent chain overlaps across batches.
// ============================================================
template<int K1, bool L0, bool POOL>
__global__ void __launch_bounds__(512, 3)
gin_fused(const __half* __restrict__ Xh,   // layers 1..3 input
          const float* __restrict__ Xf,    // L0 raw x
          const __half* __restrict__ W1, const float* __restrict__ b1,
          const __half* __restrict__ W2, const float* __restrict__ b2,
          const __half* __restrict__ Wres,
          __half* __restrict__ Out) {
    extern __shared__ char smc[];
    __half* sAh = (__half*)smc;                      // TM x LDH half   (17408 B)
    __half* sWh = (__half*)(smc + 17408);            // 128 x LDH half  (34816 B)
    float*  sD  = (float*)(smc + 17408);             // ALIAS of sWh

    int tid = threadIdx.x;
    int wid = tid >> 5;
    int r0 = blockIdx.x * TM;
    int wrow = wid & 3;
    int nbase = (wid >> 2) * 2;

    wmma::fragment<wmma::accumulator, 16, 16, 16, float> acc[2];

    auto loadW = [&](const __half* __restrict__ src, int K) {
        int n = K * 16;
        for (int idx = tid; idx < n; idx += 512) {
            int row = idx >> 4, c = idx & 15;
            uint4 v = __ldg((const uint4*)src + (size_t)row * 16 + c);
            *(uint4*)(sWh + row * LDH + c * 8) = v;
        }
    };
    auto mmaAccum = [&](int ksteps) {
        for (int k = 0; k < ksteps; k++) {
            wmma::fragment<wmma::matrix_a, 16, 16, 16, __half, wmma::row_major> af;
            wmma::load_matrix_sync(af, sAh + wrow * 16 * LDH + k * 16, LDH);
#pragma unroll
            for (int n = 0; n < 2; n++) {
                wmma::fragment<wmma::matrix_b, 16, 16, 16, __half, wmma::row_major> bf;
                wmma::load_matrix_sync(bf, sWh + k * 16 * LDH + (nbase + n) * 16, LDH);
                wmma::mma_sync(acc[n], af, bf, acc[n]);
            }
        }
    };
    auto mmaPhase = [&](int ksteps) {
#pragma unroll
        for (int n = 0; n < 2; n++) wmma::fill_fragment(acc[n], 0.f);
        mmaAccum(ksteps);
    };
    auto storeAcc = [&]() {
#pragma unroll
        for (int n = 0; n < 2; n++)
            wmma::store_matrix_sync(sD + wrow * 16 * LDF + (nbase + n) * 16, acc[n], LDF, wmma::mem_row_major);
    };

    // ---- gather into sAh (2 rows per half-warp, idx prefetch) ----
    {
        int hw = tid >> 4;
        int t = tid & 15;
#pragma unroll
        for (int rr = 0; rr < 2; rr++) {
            int row = hw * 2 + rr;
            int node = r0 + row;
            if (L0) {
                float4 a = make_float4(0.f, 0.f, 0.f, 0.f);
                if (node < NN) {
                    a = __ldg((const float4*)(Xf + (size_t)node * 64) + t);
                    int beg = __ldg(&g_rowstart[node]);
                    int end = __ldg(&g_rowstart[node + 1]);
                    int i = beg;
                    int j0 = 0, j1 = 0, j2 = 0, j3 = 0;
                    if (i + 4 <= end) {
                        j0 = __ldg(&g_csr[i + 0]); j1 = __ldg(&g_csr[i + 1]);
                        j2 = __ldg(&g_csr[i + 2]); j3 = __ldg(&g_csr[i + 3]);
                    }
                    while (i + 4 <= end) {
                        int s0 = j0, s1 = j1, s2 = j2, s3 = j3;
                        int ni = i + 4;
                        if (ni + 4 <= end) {
                            j0 = __ldg(&g_csr[ni + 0]); j1 = __ldg(&g_csr[ni + 1]);
                            j2 = __ldg(&g_csr[ni + 2]); j3 = __ldg(&g_csr[ni + 3]);
                        }
                        float4 v0 = __ldg((const float4*)(Xf + (size_t)s0 * 64) + t);
                        float4 v1 = __ldg((const float4*)(Xf + (size_t)s1 * 64) + t);
                        float4 v2 = __ldg((const float4*)(Xf + (size_t)s2 * 64) + t);
                        float4 v3 = __ldg((const float4*)(Xf + (size_t)s3 * 64) + t);
                        a.x += (v0.x + v1.x) + (v2.x + v3.x);
                        a.y += (v0.y + v1.y) + (v2.y + v3.y);
                        a.z += (v0.z + v1.z) + (v2.z + v3.z);
                        a.w += (v0.w + v1.w) + (v2.w + v3.w);
                        i = ni;
                    }
                    for (; i < end; i++) {
                        int s = __ldg(&g_csr[i]);
                        float4 v = __ldg((const float4*)(Xf + (size_t)s * 64) + t);
                        a.x += v.x; a.y += v.y; a.z += v.z; a.w += v.w;
                    }
                }
                __half2* o = (__half2*)(sAh + row * LDH + t * 4);
                o[0] = __floats2half2_rn(a.x, a.y);
                o[1] = __floats2half2_rn(a.z, a.w);
            } else {
                const uint4* Xr = (const uint4*)Xh;
                float2 a[4] = {{0.f,0.f},{0.f,0.f},{0.f,0.f},{0.f,0.f}};
                if (node < NN) {
                    uint4 v = __ldg(Xr + (size_t)node * 16 + t);
                    const __half2* hh = (const __half2*)&v;
#pragma unroll
                    for (int q = 0; q < 4; q++) a[q] = __half22float2(hh[q]);
                    int beg = __ldg(&g_rowstart[node]);
                    int end = __ldg(&g_rowstart[node + 1]);
                    int i = beg;
                    int j0 = 0, j1 = 0, j2 = 0, j3 = 0;
                    if (i + 4 <= end) {
                        j0 = __ldg(&g_csr[i + 0]); j1 = __ldg(&g_csr[i + 1]);
                        j2 = __ldg(&g_csr[i + 2]); j3 = __ldg(&g_csr[i + 3]);
                    }
                    while (i + 4 <= end) {
                        int s0 = j0, s1 = j1, s2 = j2, s3 = j3;
                        int ni = i + 4;
                        if (ni + 4 <= end) {
                            j0 = __ldg(&g_csr[ni + 0]); j1 = __ldg(&g_csr[ni + 1]);
                            j2 = __ldg(&g_csr[ni + 2]); j3 = __ldg(&g_csr[ni + 3]);
                        }
                        uint4 v0 = __ldg(Xr + (size_t)s0 * 16 + t);
                        uint4 v1 = __ldg(Xr + (size_t)s1 * 16 + t);
                        uint4 v2 = __ldg(Xr + (size_t)s2 * 16 + t);
                        uint4 v3 = __ldg(Xr + (size_t)s3 * 16 + t);
                        const __half2* h0 = (const __half2*)&v0;
                        const __half2* h1 = (const __half2*)&v1;
                        const __half2* h2 = (const __half2*)&v2;
                        const __half2* h3 = (const __half2*)&v3;
#pragma unroll
                        for (int q = 0; q < 4; q++) {
                            float2 f0 = __half22float2(h0[q]);
                            float2 f1 = __half22float2(h1[q]);
                            float2 f2 = __half22float2(h2[q]);
                            float2 f3 = __half22float2(h3[q]);
                            a[q].x += (f0.x + f1.x) + (f2.x + f3.x);
                            a[q].y += (f0.y + f1.y) + (f2.y + f3.y);
                        }
                        i = ni;
                    }
                    for (; i < end; i++) {
                        int s = __ldg(&g_csr[i]);
                        uint4 v2 = __ldg(Xr + (size_t)s * 16 + t);
                        const __half2* h2 = (const __half2*)&v2;
#pragma unroll
                        for (int q = 0; q < 4; q++) {
                            float2 f = __half22float2(h2[q]);
                            a[q].x += f.x;
                            a[q].y += f.y;
                        }
                    }
                }
                uint4 o;
                __half2* oh = (__half2*)&o;
#pragma unroll
                for (int q = 0; q < 4; q++) oh[q] = __floats2half2_rn(a[q].x, a[q].y);
                *(uint4*)(sAh + row * LDH + t * 8) = o;
            }
        }
    }
    loadW(W1, K1);
    __syncthreads();

    // ---- phase 1: T = relu(A @ W1 + b1) ----
    mmaPhase(K1 / 16);
    __syncthreads();            // all warps done reading sWh (W1)
    storeAcc();                 // write sD (aliases sWh)
    __syncthreads();
    for (int idx = tid; idx < TM * 128; idx += 512) {
        int row = idx >> 7, col = idx & 127;
        float v = fmaxf(sD[row * LDF + col] + __ldg(&b1[col]), 0.f);
        sAh[row * LDH + col] = __float2half_rn(v);
    }
    __syncthreads();            // relu reads of sD done
    loadW(W2, 128);             // overwrite aliased region with W2
    __syncthreads();

    // ---- phase 2: D = T @ W2 (acc stays in regs) ----
    mmaPhase(8);

    // ---- L0: acc += x @ Wres (register-resident residual) ----
    if (L0) {
        __syncthreads();        // all warps done reading sAh / sWh
        for (int idx = tid; idx < TM * 16; idx += 512) {
            int row = idx >> 4, c4 = idx & 15;
            float4 v = make_float4(0.f, 0.f, 0.f, 0.f);
            if (r0 + row < NN) v = __ldg((const float4*)(Xf + (size_t)(r0 + row) * 64) + c4);
            __half2* o = (__half2*)(sAh + row * LDH + c4 * 4);
            o[0] = __floats2half2_rn(v.x, v.y);
            o[1] = __floats2half2_rn(v.z, v.w);
        }
        loadW(Wres, 64);
        __syncthreads();
        mmaAccum(4);
    }
    __syncthreads();            // all warps done reading sWh
    storeAcc();                 // write sD (aliases sWh)
    __syncthreads();

    // ---- epilogue: o = relu(D + b2 + Res) ----
    for (int idx = tid; idx < TM * 32; idx += 512) {
        int row = idx >> 5, c4 = idx & 31;
        int node = r0 + row;
        if (node >= NN) continue;
        float4 d = *(float4*)(sD + row * LDF + c4 * 4);
        float4 res4 = make_float4(0.f, 0.f, 0.f, 0.f);
        if (!L0) {
            uint2 rv = __ldg((const uint2*)(Xh + (size_t)node * HD + c4 * 4));
            const __half2* rh = (const __half2*)&rv;
            float2 r01 = __half22float2(rh[0]);
            float2 r23 = __half22float2(rh[1]);
            res4 = make_float4(r01.x, r01.y, r23.x, r23.y);
        }
        int col = c4 * 4;
        float4 o;
        o.x = fmaxf(d.x + __ldg(&b2[col + 0]) + res4.x, 0.f);
        o.y = fmaxf(d.y + __ldg(&b2[col + 1]) + res4.y, 0.f);
        o.z = fmaxf(d.z + __ldg(&b2[col + 2]) + res4.z, 0.f);
        o.w = fmaxf(d.w + __ldg(&b2[col + 3]) + res4.w, 0.f);
        if (POOL) {
            int b = __ldg(&g_batch[node]);
            float* p = g_sums + (size_t)b * HD + col;
            asm volatile("red.global.add.v4.f32 [%0], {%1,%2,%3,%4};"
                         :: "l"(p), "f"(o.x), "f"(o.y), "f"(o.z), "f"(o.w) : "memory");
        } else {
            uint2 ov;
            __half2* oh = (__half2*)&ov;
            oh[0] = __floats2half2_rn(o.x, o.y);
            oh[1] = __floats2half2_rn(o.z, o.w);
            *(uint2*)(Out + (size_t)node * HD + col) = ov;
        }
    }
}

// ============================================================
// fc head (graph count via binary search on sorted batch)
// ============================================================
__global__ void __launch_bounds__(128)
head_kernel(const float* __restrict__ fW1, const float* __restrict__ fb1,
            const float* __restrict__ fW2, const float* __restrict__ fb2,
            float* __restrict__ out) {
    int g = blockIdx.x;
    int t = threadIdx.x;
    __shared__ float sp[HD];
    __shared__ float red[HD];
    __shared__ int s_cnt;
    if (t == 0) {
        int lo = 0, hi = NN;
        while (lo < hi) { int m = (lo + hi) >> 1; if (g_batch[m] < g) lo = m + 1; else hi = m; }
        int lo2 = lo, hi2 = NN;
        while (lo2 < hi2) { int m = (lo2 + hi2) >> 1; if (g_batch[m] < g + 1) lo2 = m + 1; else hi2 = m; }
        s_cnt = lo2 - lo;
    }
    __syncthreads();
    float inv = 1.0f / fmaxf((float)s_cnt, 1.0f);
    sp[t] = g_sums[(size_t)g * HD + t] * inv;
    __syncthreads();
    float acc = 0.f;
#pragma unroll 8
    for (int k = 0; k < HD; k++) acc = fmaf(sp[k], __ldg(&fW1[(size_t)k * HD + t]), acc);
    float hh = acc + __ldg(&fb1[t]);
    hh = (hh > 0.f) ? hh : hh * SLOPE;
    red[t] = hh * __ldg(&fW2[t]);
    __syncthreads();
    for (int s = 64; s > 0; s >>= 1) {
        if (t < s) red[t] += red[t + s];
        __syncthreads();
    }
    if (t == 0) out[g] = red[0] + __ldg(&fb2[0]);
}

// ============================================================
// launch
// ============================================================
extern "C" void kernel_launch(void* const* d_in, const int* in_sizes, int n_in,
                              void* d_out, int out_size) {
    const float* x     = (const float*)d_in[0];
    const void*  ei    = d_in[1];
    const void*  batch = d_in[2];
    const float* l0_W1   = (const float*)d_in[3];
    const float* l0_b1   = (const float*)d_in[4];
    const float* l0_W2   = (const float*)d_in[5];
    const float* l0_b2   = (const float*)d_in[6];
    const float* l0_Wres = (const float*)d_in[7];
    const float* Ws1 = (const float*)d_in[8];
    const float* bs1 = (const float*)d_in[9];
    const float* Ws2 = (const float*)d_in[10];
    const float* bs2 = (const float*)d_in[11];
    const float* fW1 = (const float*)d_in[12];
    const float* fb1 = (const float*)d_in[13];
    const float* fW2 = (const float*)d_in[14];
    const float* fb2 = (const float*)d_in[15];
    float* out = (float*)d_out;

    __half *h0, *h1, *wh;
    cudaGetSymbolAddress((void**)&h0, g_h0);
    cudaGetSymbolAddress((void**)&h1, g_h1);
    cudaGetSymbolAddress((void**)&wh, g_wh);

    const int DSM = 52224;   // sAh(17408) + sWh(34816); sD aliases sWh
    static bool attr_set = false;
    if (!attr_set) {
        cudaFuncSetAttribute(gin_fused<64, true, false>,   cudaFuncAttributeMaxDynamicSharedMemorySize, DSM);
        cudaFuncSetAttribute(gin_fused<128, false, false>, cudaFuncAttributeMaxDynamicSharedMemorySize, DSM);
        cudaFuncSetAttribute(gin_fused<128, false, true>,  cudaFuncAttributeMaxDynamicSharedMemorySize, DSM);
        attr_set = true;
    }

    // ---- setup ----
    zero_detect<<<(NG * HD + 255) / 256, 256>>>((const int*)ei);
    hist_conv<<<(NE + 255) / 256, 256>>>(ei, batch);
    scan_deg<<<1, 1024>>>();
    fill_csr_convw<<<(NE + 255) / 256, 256>>>(ei, l0_W1, l0_W2, l0_Wres, Ws1, Ws2);

    const int blocks = (NN + TM - 1) / TM;   // 782

    // ---- 4 fused GIN layers ----
    gin_fused<64, true, false><<<blocks, 512, DSM>>>(
        nullptr, x, wh + OW_W10, l0_b1, wh + OW_W20, l0_b2, wh + OW_RES, h0);
    gin_fused<128, false, false><<<blocks, 512, DSM>>>(
        h0, nullptr, wh + OW_WS1, bs1, wh + OW_WS2, bs2, nullptr, h1);
    gin_fused<128, false, false><<<blocks, 512, DSM>>>(
        h1, nullptr, wh + OW_WS1 + 16384, bs1 + HD, wh + OW_WS2 + 16384, bs2 + HD, nullptr, h0);
    gin_fused<128, false, true><<<blocks, 512, DSM>>>(
        h0, nullptr, wh + OW_WS1 + 32768, bs1 + 2 * HD, wh + OW_WS2 + 32768, bs2 + 2 * HD, nullptr, nullptr);

    // ---- head ----
    head_kernel<<<NG, 128>>>(fW1, fb1, fW2, fb2, out);
}

// round 14
// speedup vs baseline: 3.3188x; 1.0247x over previous
#include <cuda_runtime.h>
#include <cuda_fp16.h>
#include <mma.h>
#include <cstdint>

using namespace nvcuda;

// ---------------- problem constants ----------------
constexpr int NN = 50000;
constexpr int NE = 800000;
constexpr int IND = 64;
constexpr int HD = 128;
constexpr int NG = 1024;
constexpr float SLOPE = 0.01f;

constexpr int TM  = 48;    // rows per block tile (3 wmma row-tiles)
constexpr int LDH = 136;   // half smem leading dim
constexpr int LDF = 132;   // float smem leading dim
constexpr int NT  = 384;   // threads per block (12 warps)

// ---------------- scratch (device globals) ----------------
__device__ __align__(256) __half g_h0[(size_t)NN * HD];
__device__ __align__(256) __half g_h1[(size_t)NN * HD];
__device__ __align__(256) __half g_wh[131072];       // all weights, fp16
__device__ __align__(256) float g_sums[(size_t)NG * HD];
__device__ __align__(256) int   g_batch[NN];
__device__ __align__(256) int   g_deg[NN];
__device__ __align__(256) int   g_cur[NN];
__device__ __align__(256) int   g_rowstart[NN + 1];
__device__ __align__(256) int   g_csr[NE];
__device__ int g_is64;

// weight offsets in g_wh (halves)
constexpr int OW_RES = 0;        // [64][128]
constexpr int OW_W10 = 8192;     // [64][128]
constexpr int OW_W20 = 16384;    // [128][128]
constexpr int OW_WS1 = 32768;    // 3 x [128][128]
constexpr int OW_WS2 = 81920;    // 3 x [128][128]

// ============================================================
// setup kernels
// ============================================================
__global__ void zero_detect(const int* __restrict__ rawE) {
    int i = blockIdx.x * blockDim.x + threadIdx.x;
    if (i < NN) { g_deg[i] = 0; g_cur[i] = 0; }
    if (i < NG * HD) g_sums[i] = 0.f;
    if (blockIdx.x == 0) {
        __shared__ int s_any;
        if (threadIdx.x == 0) s_any = 0;
        __syncthreads();
        int bad = 0;
        for (int k = threadIdx.x; k < 4096; k += blockDim.x) bad |= rawE[2 * k + 1];
        if (bad) atomicOr(&s_any, 1);
        __syncthreads();
        if (threadIdx.x == 0) g_is64 = (s_any == 0) ? 1 : 0;
    }
}
__global__ void hist_conv(const void* __restrict__ rawE, const void* __restrict__ rawB) {
    int i = blockIdx.x * blockDim.x + threadIdx.x;
    int is64 = g_is64;
    if (i < NE) {
        int d = is64 ? (int)((const long long*)rawE)[NE + i] : ((const int*)rawE)[NE + i];
        atomicAdd(&g_deg[d], 1);
    }
    if (i < NN) {
        g_batch[i] = is64 ? (int)((const long long*)rawB)[i] : ((const int*)rawB)[i];
    }
}
__global__ void __launch_bounds__(1024) scan_deg() {
    __shared__ int part[1024];
    int tid = threadIdx.x;
    const int CH = (NN + 1023) / 1024;
    int base = tid * CH;
    int s = 0;
    for (int i = 0; i < CH; i++) {
        int idx = base + i;
        if (idx < NN) s += g_deg[idx];
    }
    part[tid] = s;
    __syncthreads();
    for (int off = 1; off < 1024; off <<= 1) {
        int v = (tid >= off) ? part[tid - off] : 0;
        __syncthreads();
        part[tid] += v;
        __syncthreads();
    }
    int run = (tid > 0) ? part[tid - 1] : 0;
    for (int i = 0; i < CH; i++) {
        int idx = base + i;
        if (idx < NN) {
            g_rowstart[idx] = run;
            run += g_deg[idx];
        }
    }
    if (tid == 1023) g_rowstart[NN] = run;
}
// fill CSR + convert weights (independent work fused into one launch)
__global__ void fill_csr_convw(const void* __restrict__ rawE,
                               const float* __restrict__ l0_W1, const float* __restrict__ l0_W2,
                               const float* __restrict__ l0_Wres,
                               const float* __restrict__ Ws1, const float* __restrict__ Ws2) {
    int e = blockIdx.x * blockDim.x + threadIdx.x;
    if (e < 131072) {
        float v;
        if (e < 8192)        v = __ldg(&l0_Wres[e]);
        else if (e < 16384)  v = __ldg(&l0_W1[e - 8192]);
        else if (e < 32768)  v = __ldg(&l0_W2[e - 16384]);
        else if (e < 81920)  v = __ldg(&Ws1[e - 32768]);
        else                 v = __ldg(&Ws2[e - 81920]);
        g_wh[e] = __float2half_rn(v);
    }
    if (e >= NE) return;
    int is64 = g_is64;
    int s = is64 ? (int)((const long long*)rawE)[e]      : ((const int*)rawE)[e];
    int d = is64 ? (int)((const long long*)rawE)[NE + e] : ((const int*)rawE)[NE + e];
    int p = atomicAdd(&g_cur[d], 1);
    g_csr[g_rowstart[d] + p] = s;
}

// ============================================================
// fused GIN layer, 48-row tile, smem-aliased D staging, 4 CTAs/SM:
//   A[row] = X[node] + sum_{src in csr[node]} X[src]
//   Out = relu( relu(A@W1 + b1) @ W2 + b2 + Res )
// 12 warps: wrow = wid % 3 (3 row-tiles), ncg = wid / 3 (4 col-groups
// of 32 cols = 2 fragments each). sD aliases sWh.
// ============================================================
template<int K1, bool L0, bool POOL>
__global__ void __launch_bounds__(NT, 4)
gin_fused(const __half* __restrict__ Xh,   // layers 1..3 input
          const float* __restrict__ Xf,    // L0 raw x
          const __half* __restrict__ W1, const float* __restrict__ b1,
          const __half* __restrict__ W2, const float* __restrict__ b2,
          const __half* __restrict__ Wres,
          __half* __restrict__ Out) {
    extern __shared__ char smc[];
    __half* sAh = (__half*)smc;                      // TM x LDH half   (13056 B)
    __half* sWh = (__half*)(smc + 13056);            // 128 x LDH half  (34816 B)
    float*  sD  = (float*)(smc + 13056);             // ALIAS of sWh (TM x LDF = 25344 B)

    int tid = threadIdx.x;
    int wid = tid >> 5;
    int r0 = blockIdx.x * TM;
    int wrow = wid % 3;            // row-tile 0..2
    int ncg  = wid / 3;            // col-group 0..3 (32 cols each)

    wmma::fragment<wmma::accumulator, 16, 16, 16, float> acc[2];

    auto loadW = [&](const __half* __restrict__ src, int K) {
        int n = K * 16;
        for (int idx = tid; idx < n; idx += NT) {
            int row = idx >> 4, c = idx & 15;
            uint4 v = __ldg((const uint4*)src + (size_t)row * 16 + c);
            *(uint4*)(sWh + row * LDH + c * 8) = v;
        }
    };
    auto mmaAccum = [&](int ksteps) {
        for (int k = 0; k < ksteps; k++) {
            wmma::fragment<wmma::matrix_a, 16, 16, 16, __half, wmma::row_major> af;
            wmma::load_matrix_sync(af, sAh + wrow * 16 * LDH + k * 16, LDH);
#pragma unroll
            for (int n = 0; n < 2; n++) {
                wmma::fragment<wmma::matrix_b, 16, 16, 16, __half, wmma::row_major> bf;
                wmma::load_matrix_sync(bf, sWh + k * 16 * LDH + ncg * 32 + n * 16, LDH);
                wmma::mma_sync(acc[n], af, bf, acc[n]);
            }
        }
    };
    auto mmaPhase = [&](int ksteps) {
#pragma unroll
        for (int n = 0; n < 2; n++) wmma::fill_fragment(acc[n], 0.f);
        mmaAccum(ksteps);
    };
    auto storeAcc = [&]() {
#pragma unroll
        for (int n = 0; n < 2; n++)
            wmma::store_matrix_sync(sD + wrow * 16 * LDF + ncg * 32 + n * 16, acc[n], LDF, wmma::mem_row_major);
    };

    // ---- gather into sAh (2 rows per half-warp, idx prefetch) ----
    {
        int hw = tid >> 4;        // half-warp 0..23
        int t = tid & 15;
#pragma unroll
        for (int rr = 0; rr < 2; rr++) {
            int row = hw * 2 + rr;
            int node = r0 + row;
            if (L0) {
                float4 a = make_float4(0.f, 0.f, 0.f, 0.f);
                if (node < NN) {
                    a = __ldg((const float4*)(Xf + (size_t)node * 64) + t);
                    int beg = __ldg(&g_rowstart[node]);
                    int end = __ldg(&g_rowstart[node + 1]);
                    int i = beg;
                    int j0 = 0, j1 = 0, j2 = 0, j3 = 0;
                    if (i + 4 <= end) {
                        j0 = __ldg(&g_csr[i + 0]); j1 = __ldg(&g_csr[i + 1]);
                        j2 = __ldg(&g_csr[i + 2]); j3 = __ldg(&g_csr[i + 3]);
                    }
                    while (i + 4 <= end) {
                        int s0 = j0, s1 = j1, s2 = j2, s3 = j3;
                        int ni = i + 4;
                        if (ni + 4 <= end) {
                            j0 = __ldg(&g_csr[ni + 0]); j1 = __ldg(&g_csr[ni + 1]);
                            j2 = __ldg(&g_csr[ni + 2]); j3 = __ldg(&g_csr[ni + 3]);
                        }
                        float4 v0 = __ldg((const float4*)(Xf + (size_t)s0 * 64) + t);
                        float4 v1 = __ldg((const float4*)(Xf + (size_t)s1 * 64) + t);
                        float4 v2 = __ldg((const float4*)(Xf + (size_t)s2 * 64) + t);
                        float4 v3 = __ldg((const float4*)(Xf + (size_t)s3 * 64) + t);
                        a.x += (v0.x + v1.x) + (v2.x + v3.x);
                        a.y += (v0.y + v1.y) + (v2.y + v3.y);
                        a.z += (v0.z + v1.z) + (v2.z + v3.z);
                        a.w += (v0.w + v1.w) + (v2.w + v3.w);
                        i = ni;
                    }
                    for (; i < end; i++) {
                        int s = __ldg(&g_csr[i]);
                        float4 v = __ldg((const float4*)(Xf + (size_t)s * 64) + t);
                        a.x += v.x; a.y += v.y; a.z += v.z; a.w += v.w;
                    }
                }
                __half2* o = (__half2*)(sAh + row * LDH + t * 4);
                o[0] = __floats2half2_rn(a.x, a.y);
                o[1] = __floats2half2_rn(a.z, a.w);
            } else {
                const uint4* Xr = (const uint4*)Xh;
                float2 a[4] = {{0.f,0.f},{0.f,0.f},{0.f,0.f},{0.f,0.f}};
                if (node < NN) {
                    uint4 v = __ldg(Xr + (size_t)node * 16 + t);
                    const __half2* hh = (const __half2*)&v;
#pragma unroll
                    for (int q = 0; q < 4; q++) a[q] = __half22float2(hh[q]);
                    int beg = __ldg(&g_rowstart[node]);
                    int end = __ldg(&g_rowstart[node + 1]);
                    int i = beg;
                    int j0 = 0, j1 = 0, j2 = 0, j3 = 0;
                    if (i + 4 <= end) {
                        j0 = __ldg(&g_csr[i + 0]); j1 = __ldg(&g_csr[i + 1]);
                        j2 = __ldg(&g_csr[i + 2]); j3 = __ldg(&g_csr[i + 3]);
                    }
                    while (i + 4 <= end) {
                        int s0 = j0, s1 = j1, s2 = j2, s3 = j3;
                        int ni = i + 4;
                        if (ni + 4 <= end) {
                            j0 = __ldg(&g_csr[ni + 0]); j1 = __ldg(&g_csr[ni + 1]);
                            j2 = __ldg(&g_csr[ni + 2]); j3 = __ldg(&g_csr[ni + 3]);
                        }
                        uint4 v0 = __ldg(Xr + (size_t)s0 * 16 + t);
                        uint4 v1 = __ldg(Xr + (size_t)s1 * 16 + t);
                        uint4 v2 = __ldg(Xr + (size_t)s2 * 16 + t);
                        uint4 v3 = __ldg(Xr + (size_t)s3 * 16 + t);
                        const __half2* h0 = (const __half2*)&v0;
                        const __half2* h1 = (const __half2*)&v1;
                        const __half2* h2 = (const __half2*)&v2;
                        const __half2* h3 = (const __half2*)&v3;
#pragma unroll
                        for (int q = 0; q < 4; q++) {
                            float2 f0 = __half22float2(h0[q]);
                            float2 f1 = __half22float2(h1[q]);
                            float2 f2 = __half22float2(h2[q]);
                            float2 f3 = __half22float2(h3[q]);
                            a[q].x += (f0.x + f1.x) + (f2.x + f3.x);
                            a[q].y += (f0.y + f1.y) + (f2.y + f3.y);
                        }
                        i = ni;
                    }
                    for (; i < end; i++) {
                        int s = __ldg(&g_csr[i]);
                        uint4 v2 = __ldg(Xr + (size_t)s * 16 + t);
                        const __half2* h2 = (const __half2*)&v2;
#pragma unroll
                        for (int q = 0; q < 4; q++) {
                            float2 f = __half22float2(h2[q]);
                            a[q].x += f.x;
                            a[q].y += f.y;
                        }
                    }
                }
                uint4 o;
                __half2* oh = (__half2*)&o;
#pragma unroll
                for (int q = 0; q < 4; q++) oh[q] = __floats2half2_rn(a[q].x, a[q].y);
                *(uint4*)(sAh + row * LDH + t * 8) = o;
            }
        }
    }
    loadW(W1, K1);
    __syncthreads();

    // ---- phase 1: T = relu(A @ W1 + b1) ----
    mmaPhase(K1 / 16);
    __syncthreads();            // all warps done reading sWh (W1)
    storeAcc();                 // write sD (aliases sWh)
    __syncthreads();
    for (int idx = tid; idx < TM * 128; idx += NT) {
        int row = idx >> 7, col = idx & 127;
        float v = fmaxf(sD[row * LDF + col] + __ldg(&b1[col]), 0.f);
        sAh[row * LDH + col] = __float2half_rn(v);
    }
    __syncthreads();            // relu reads of sD done
    loadW(W2, 128);             // overwrite aliased region with W2
    __syncthreads();

    // ---- phase 2: D = T @ W2 (acc stays in regs) ----
    mmaPhase(8);

    // ---- L0: acc += x @ Wres (register-resident residual) ----
    if (L0) {
        __syncthreads();        // all warps done reading sAh / sWh
        for (int idx = tid; idx < TM * 16; idx += NT) {
            int row = idx >> 4, c4 = idx & 15;
            float4 v = make_float4(0.f, 0.f, 0.f, 0.f);
            if (r0 + row < NN) v = __ldg((const float4*)(Xf + (size_t)(r0 + row) * 64) + c4);
            __half2* o = (__half2*)(sAh + row * LDH + c4 * 4);
            o[0] = __floats2half2_rn(v.x, v.y);
            o[1] = __floats2half2_rn(v.z, v.w);
        }
        loadW(Wres, 64);
        __syncthreads();
        mmaAccum(4);
    }
    __syncthreads();            // all warps done reading sWh
    storeAcc();                 // write sD (aliases sWh)
    __syncthreads();

    // ---- epilogue: o = relu(D + b2 + Res) ----
    for (int idx = tid; idx < TM * 32; idx += NT) {
        int row = idx >> 5, c4 = idx & 31;
        int node = r0 + row;
        if (node >= NN) continue;
        float4 d = *(float4*)(sD + row * LDF + c4 * 4);
        float4 res4 = make_float4(0.f, 0.f, 0.f, 0.f);
        if (!L0) {
            uint2 rv = __ldg((const uint2*)(Xh + (size_t)node * HD + c4 * 4));
            const __half2* rh = (const __half2*)&rv;
            float2 r01 = __half22float2(rh[0]);
            float2 r23 = __half22float2(rh[1]);
            res4 = make_float4(r01.x, r01.y, r23.x, r23.y);
        }
        int col = c4 * 4;
        float4 o;
        o.x = fmaxf(d.x + __ldg(&b2[col + 0]) + res4.x, 0.f);
        o.y = fmaxf(d.y + __ldg(&b2[col + 1]) + res4.y, 0.f);
        o.z = fmaxf(d.z + __ldg(&b2[col + 2]) + res4.z, 0.f);
        o.w = fmaxf(d.w + __ldg(&b2[col + 3]) + res4.w, 0.f);
        if (POOL) {
            int b = __ldg(&g_batch[node]);
            float* p = g_sums + (size_t)b * HD + col;
            asm volatile("red.global.add.v4.f32 [%0], {%1,%2,%3,%4};"
                         :: "l"(p), "f"(o.x), "f"(o.y), "f"(o.z), "f"(o.w) : "memory");
        } else {
            uint2 ov;
            __half2* oh = (__half2*)&ov;
            oh[0] = __floats2half2_rn(o.x, o.y);
            oh[1] = __floats2half2_rn(o.z, o.w);
            *(uint2*)(Out + (size_t)node * HD + col) = ov;
        }
    }
}

// ============================================================
// fc head (graph count via binary search on sorted batch)
// ============================================================
__global__ void __launch_bounds__(128)
head_kernel(const float* __restrict__ fW1, const float* __restrict__ fb1,
            const float* __restrict__ fW2, const float* __restrict__ fb2,
            float* __restrict__ out) {
    int g = blockIdx.x;
    int t = threadIdx.x;
    __shared__ float sp[HD];
    __shared__ float red[HD];
    __shared__ int s_cnt;
    if (t == 0) {
        int lo = 0, hi = NN;
        while (lo < hi) { int m = (lo + hi) >> 1; if (g_batch[m] < g) lo = m + 1; else hi = m; }
        int lo2 = lo, hi2 = NN;
        while (lo2 < hi2) { int m = (lo2 + hi2) >> 1; if (g_batch[m] < g + 1) lo2 = m + 1; else hi2 = m; }
        s_cnt = lo2 - lo;
    }
    __syncthreads();
    float inv = 1.0f / fmaxf((float)s_cnt, 1.0f);
    sp[t] = g_sums[(size_t)g * HD + t] * inv;
    __syncthreads();
    float acc = 0.f;
#pragma unroll 8
    for (int k = 0; k < HD; k++) acc = fmaf(sp[k], __ldg(&fW1[(size_t)k * HD + t]), acc);
    float hh = acc + __ldg(&fb1[t]);
    hh = (hh > 0.f) ? hh : hh * SLOPE;
    red[t] = hh * __ldg(&fW2[t]);
    __syncthreads();
    for (int s = 64; s > 0; s >>= 1) {
        if (t < s) red[t] += red[t + s];
        __syncthreads();
    }
    if (t == 0) out[g] = red[0] + __ldg(&fb2[0]);
}

// ============================================================
// launch
// ============================================================
extern "C" void kernel_launch(void* const* d_in, const int* in_sizes, int n_in,
                              void* d_out, int out_size) {
    const float* x     = (const float*)d_in[0];
    const void*  ei    = d_in[1];
    const void*  batch = d_in[2];
    const float* l0_W1   = (const float*)d_in[3];
    const float* l0_b1   = (const float*)d_in[4];
    const float* l0_W2   = (const float*)d_in[5];
    const float* l0_b2   = (const float*)d_in[6];
    const float* l0_Wres = (const float*)d_in[7];
    const float* Ws1 = (const float*)d_in[8];
    const float* bs1 = (const float*)d_in[9];
    const float* Ws2 = (const float*)d_in[10];
    const float* bs2 = (const float*)d_in[11];
    const float* fW1 = (const float*)d_in[12];
    const float* fb1 = (const float*)d_in[13];
    const float* fW2 = (const float*)d_in[14];
    const float* fb2 = (const float*)d_in[15];
    float* out = (float*)d_out;

    __half *h0, *h1, *wh;
    cudaGetSymbolAddress((void**)&h0, g_h0);
    cudaGetSymbolAddress((void**)&h1, g_h1);
    cudaGetSymbolAddress((void**)&wh, g_wh);

    const int DSM = 47872;   // sAh(13056) + sWh(34816); sD aliases sWh
    static bool attr_set = false;
    if (!attr_set) {
        cudaFuncSetAttribute(gin_fused<64, true, false>,   cudaFuncAttributeMaxDynamicSharedMemorySize, DSM);
        cudaFuncSetAttribute(gin_fused<128, false, false>, cudaFuncAttributeMaxDynamicSharedMemorySize, DSM);
        cudaFuncSetAttribute(gin_fused<128, false, true>,  cudaFuncAttributeMaxDynamicSharedMemorySize, DSM);
        // maximize smem carveout so 4 CTAs/SM (191.5 KB) fit
        cudaFuncSetAttribute(gin_fused<64, true, false>,   cudaFuncAttributePreferredSharedMemoryCarveout, 100);
        cudaFuncSetAttribute(gin_fused<128, false, false>, cudaFuncAttributePreferredSharedMemoryCarveout, 100);
        cudaFuncSetAttribute(gin_fused<128, false, true>,  cudaFuncAttributePreferredSharedMemoryCarveout, 100);
        attr_set = true;
    }

    // ---- setup ----
    zero_detect<<<(NG * HD + 255) / 256, 256>>>((const int*)ei);
    hist_conv<<<(NE + 255) / 256, 256>>>(ei, batch);
    scan_deg<<<1, 1024>>>();
    fill_csr_convw<<<(NE + 255) / 256, 256>>>(ei, l0_W1, l0_W2, l0_Wres, Ws1, Ws2);

    const int blocks = (NN + TM - 1) / TM;   // 1042

    // ---- 4 fused GIN layers ----
    gin_fused<64, true, false><<<blocks, NT, DSM>>>(
        nullptr, x, wh + OW_W10, l0_b1, wh + OW_W20, l0_b2, wh + OW_RES, h0);
    gin_fused<128, false, false><<<blocks, NT, DSM>>>(
        h0, nullptr, wh + OW_WS1, bs1, wh + OW_WS2, bs2, nullptr, h1);
    gin_fused<128, false, false><<<blocks, NT, DSM>>>(
        h1, nullptr, wh + OW_WS1 + 16384, bs1 + HD, wh + OW_WS2 + 16384, bs2 + HD, nullptr, h0);
    gin_fused<128, false, true><<<blocks, NT, DSM>>>(
        h0, nullptr, wh + OW_WS1 + 32768, bs1 + 2 * HD, wh + OW_WS2 + 32768, bs2 + 2 * HD, nullptr, nullptr);

    // ---- head ----
    head_kernel<<<NG, 128>>>(fW1, fb1, fW2, fb2, out);
}